// round 1
// baseline (speedup 1.0000x reference)
#include <cuda_runtime.h>
#include <cuda_bf16.h>
#include <math.h>

// Problem constants
#define BB   16        // batch
#define CIN  512
#define COUT 512
#define HW   4096      // 64*64
#define MCB  192       // codebook size
#define EPS_BN 1e-5f

// GEMM tiling: 128(M) x 64(N) x 16(K), 256 threads, 8x4 micro-tile
#define TILE_M 128
#define TILE_N 64
#define TILE_K 16
#define PAD_M  132     // +4 pad, keeps 16B row alignment (132*4=528)
#define PAD_N  68      // +4 pad, keeps 16B row alignment (68*4=272)
#define NTHREADS 256

// -------------------- scratch (device globals, no alloc) --------------------
__device__ float g_buf1[(size_t)BB * COUT * HW];   // 134 MB
__device__ float g_buf2[(size_t)BB * CIN * HW];    // 134 MB
__device__ float g_att [(size_t)BB * HW * MCB];    // 50 MB
__device__ float g_colsum[BB * MCB];
__device__ float g_scale[CIN];
__device__ float g_shift[CIN];

// -------------------- generic tiled SGEMM --------------------
// C[m,n] = sum_k A(m,k)*B(k,n) (+ bias[m] if BIAS), per-batch strides aS/bS/cS.
// TA: A stored [K,M] (A[k*Md+m]); else A stored [M,K] (A[m*Kd+k])
// TB: B stored [N,K] (B[n*Kd+k]); else B stored [K,N] (B[k*Nd+n])
template<bool TA, bool TB, bool BIAS>
__global__ __launch_bounds__(NTHREADS)
void sgemm(const float* __restrict__ Ag, const float* __restrict__ Bg,
           const float* __restrict__ bias, float* __restrict__ Cg,
           int Md, int Nd, int Kd,
           size_t aS, size_t bS, size_t cS)
{
    __shared__ __align__(16) float As[TILE_K][PAD_M];
    __shared__ __align__(16) float Bs[TILE_K][PAD_N];

    const int lid = threadIdx.x;
    const int tx = lid & 15;   // n dir: 16 * 4 = 64
    const int ty = lid >> 4;   // m dir: 16 * 8 = 128
    const int n0 = blockIdx.x * TILE_N;
    const int m0 = blockIdx.y * TILE_M;
    const int z  = blockIdx.z;

    const float* A  = Ag + (size_t)z * aS;
    const float* Bm = Bg + (size_t)z * bS;
    float* C = Cg + (size_t)z * cS;

    float acc[8][4];
#pragma unroll
    for (int i = 0; i < 8; ++i)
#pragma unroll
        for (int j = 0; j < 4; ++j) acc[i][j] = 0.f;

    for (int k0 = 0; k0 < Kd; k0 += TILE_K) {
        // ---- load A tile ----
        if (TA) {
            const int kr = lid >> 4;          // 0..15
            const int mc = (lid & 15) << 3;   // 0..120
            const float* src = A + (size_t)(k0 + kr) * Md + m0 + mc;
            float4 v0 = *(const float4*)(src);
            float4 v1 = *(const float4*)(src + 4);
            *(float4*)&As[kr][mc]     = v0;
            *(float4*)&As[kr][mc + 4] = v1;
        } else {
            const int ar = lid >> 2;          // 0..63
            const int ac = (lid & 3) << 2;    // 0,4,8,12
#pragma unroll
            for (int it = 0; it < 2; ++it) {
                const int m = ar + it * 64;
                float4 v = *(const float4*)(A + (size_t)(m0 + m) * Kd + k0 + ac);
                As[ac + 0][m] = v.x;
                As[ac + 1][m] = v.y;
                As[ac + 2][m] = v.z;
                As[ac + 3][m] = v.w;
            }
        }
        // ---- load B tile ----
        if (TB) {
            const int nr = lid >> 2;          // 0..63
            const int kc = (lid & 3) << 2;    // 0,4,8,12
            float4 v = *(const float4*)(Bm + (size_t)(n0 + nr) * Kd + k0 + kc);
            Bs[kc + 0][nr] = v.x;
            Bs[kc + 1][nr] = v.y;
            Bs[kc + 2][nr] = v.z;
            Bs[kc + 3][nr] = v.w;
        } else {
            const int br = lid >> 4;          // 0..15
            const int bc = (lid & 15) << 2;   // 0..60
            float4 v = *(const float4*)(Bm + (size_t)(k0 + br) * Nd + n0 + bc);
            *(float4*)&Bs[br][bc] = v;
        }
        __syncthreads();

#pragma unroll
        for (int kk = 0; kk < TILE_K; ++kk) {
            float4 a0 = *(const float4*)&As[kk][ty * 8];
            float4 a1 = *(const float4*)&As[kk][ty * 8 + 4];
            float4 b0 = *(const float4*)&Bs[kk][tx * 4];
            float a[8] = {a0.x, a0.y, a0.z, a0.w, a1.x, a1.y, a1.z, a1.w};
            float bv[4] = {b0.x, b0.y, b0.z, b0.w};
#pragma unroll
            for (int i = 0; i < 8; ++i)
#pragma unroll
                for (int j = 0; j < 4; ++j)
                    acc[i][j] = fmaf(a[i], bv[j], acc[i][j]);
        }
        __syncthreads();
    }

#pragma unroll
    for (int i = 0; i < 8; ++i) {
        const int m = m0 + ty * 8 + i;
        float bv = BIAS ? bias[m] : 0.f;
        float4 o;
        o.x = acc[i][0] + bv;
        o.y = acc[i][1] + bv;
        o.z = acc[i][2] + bv;
        o.w = acc[i][3] + bv;
        *(float4*)(C + (size_t)m * Nd + n0 + tx * 4) = o;
    }
}

// ------------- softmax over k (192) + column-sum accumulation -------------
__global__ void softmax_colsum_kernel(float* __restrict__ att, float* __restrict__ colsum)
{
    const int warp = threadIdx.x >> 5;
    const int lane = threadIdx.x & 31;
    const int b = blockIdx.y;
    const int rowBase = blockIdx.x * 256 + warp * 32;

    float cacc[6] = {0.f, 0.f, 0.f, 0.f, 0.f, 0.f};

    for (int r = 0; r < 32; ++r) {
        const int n = rowBase + r;
        float* p = att + ((size_t)b * HW + n) * MCB;
        float v[6];
        float mx = -1e30f;
#pragma unroll
        for (int j = 0; j < 6; ++j) { v[j] = p[j * 32 + lane]; mx = fmaxf(mx, v[j]); }
#pragma unroll
        for (int o = 16; o > 0; o >>= 1) mx = fmaxf(mx, __shfl_xor_sync(0xffffffffu, mx, o));
        float s = 0.f;
#pragma unroll
        for (int j = 0; j < 6; ++j) { v[j] = expf(v[j] - mx); s += v[j]; }
#pragma unroll
        for (int o = 16; o > 0; o >>= 1) s += __shfl_xor_sync(0xffffffffu, s, o);
        const float inv = 1.f / s;
#pragma unroll
        for (int j = 0; j < 6; ++j) {
            float ov = v[j] * inv;
            p[j * 32 + lane] = ov;
            cacc[j] += ov;
        }
    }
#pragma unroll
    for (int j = 0; j < 6; ++j)
        atomicAdd(&colsum[b * MCB + j * 32 + lane], cacc[j]);
}

__global__ void zero_colsum_kernel(float* cs)
{
    int i = blockIdx.x * 1024 + threadIdx.x;
    if (i < BB * MCB) cs[i] = 0.f;
}

__global__ void rcp_colsum_kernel(float* cs)
{
    int i = blockIdx.x * 1024 + threadIdx.x;
    if (i < BB * MCB) cs[i] = 1.f / (1e-6f + cs[i]);
}

// att[b,n,k] *= rcp[b,k]   (float4 along k: 192/4 = 48 per row)
__global__ void scale_att_kernel(float* __restrict__ att, const float* __restrict__ rcp)
{
    size_t i = (size_t)blockIdx.x * blockDim.x + threadIdx.x;   // float4 index
    const int k4 = (int)(i % 48);
    const size_t row = i / 48;
    const int b = (int)(row >> 12);
    float4 v = ((float4*)att)[i];
    const float4 r = ((const float4*)rcp)[b * 48 + k4];
    v.x *= r.x; v.y *= r.y; v.z *= r.z; v.w *= r.w;
    ((float4*)att)[i] = v;
}

// ---------------- BN batch-stats: fold gamma/beta into scale/shift ----------
__global__ void bn_stats_kernel(const float* __restrict__ t,
                                const float* __restrict__ gamma, const float* __restrict__ beta,
                                float* __restrict__ scale, float* __restrict__ shift)
{
    const int c = blockIdx.x;
    const int tid = threadIdx.x;
    float s = 0.f, s2 = 0.f;
    for (int b = 0; b < BB; ++b) {
        const float4* p = (const float4*)(t + ((size_t)b * CIN + c) * HW);
        for (int i = tid; i < HW / 4; i += 256) {
            float4 v = p[i];
            s  += v.x + v.y + v.z + v.w;
            s2 += v.x * v.x + v.y * v.y + v.z * v.z + v.w * v.w;
        }
    }
    __shared__ float rs[256];
    __shared__ float rs2[256];
    rs[tid] = s; rs2[tid] = s2;
    __syncthreads();
    for (int o = 128; o > 0; o >>= 1) {
        if (tid < o) { rs[tid] += rs[tid + o]; rs2[tid] += rs2[tid + o]; }
        __syncthreads();
    }
    if (tid == 0) {
        const float N = (float)((size_t)BB * HW);
        float mean = rs[0] / N;
        float var = rs2[0] / N - mean * mean;
        float sc = gamma[c] * rsqrtf(var + EPS_BN);
        scale[c] = sc;
        shift[c] = beta[c] - mean * sc;
    }
}

// out = relu(scale*t + shift) + x
__global__ void bn_apply_res_kernel(const float* __restrict__ t, const float* __restrict__ x,
                                    const float* __restrict__ scale, const float* __restrict__ shift,
                                    float* __restrict__ out)
{
    size_t i = (size_t)blockIdx.x * blockDim.x + threadIdx.x;   // float4 index
    const int c = (int)((i >> 10) & 511);
    const float sc = scale[c], sh = shift[c];
    float4 v = ((const float4*)t)[i];
    float4 xv = ((const float4*)x)[i];
    v.x = fmaxf(fmaf(sc, v.x, sh), 0.f) + xv.x;
    v.y = fmaxf(fmaf(sc, v.y, sh), 0.f) + xv.y;
    v.z = fmaxf(fmaf(sc, v.z, sh), 0.f) + xv.z;
    v.w = fmaxf(fmaf(sc, v.w, sh), 0.f) + xv.w;
    ((float4*)out)[i] = v;
}

// out = relu(scale*t + shift)
__global__ void bn_apply_kernel(const float* __restrict__ t,
                                const float* __restrict__ scale, const float* __restrict__ shift,
                                float* __restrict__ out)
{
    size_t i = (size_t)blockIdx.x * blockDim.x + threadIdx.x;
    const int c = (int)((i >> 10) & 511);
    const float sc = scale[c], sh = shift[c];
    float4 v = ((const float4*)t)[i];
    v.x = fmaxf(fmaf(sc, v.x, sh), 0.f);
    v.y = fmaxf(fmaf(sc, v.y, sh), 0.f);
    v.z = fmaxf(fmaf(sc, v.z, sh), 0.f);
    v.w = fmaxf(fmaf(sc, v.w, sh), 0.f);
    ((float4*)out)[i] = v;
}

// -------------------- launch --------------------
extern "C" void kernel_launch(void* const* d_in, const int* in_sizes, int n_in,
                              void* d_out, int out_size)
{
    const float* x       = (const float*)d_in[0];
    const float* centers = (const float*)d_in[1];
    const float* conv1_w = (const float*)d_in[2];
    const float* conv1_b = (const float*)d_in[3];
    const float* conv2_w = (const float*)d_in[4];
    const float* bn2_g   = (const float*)d_in[5];
    const float* bn2_b   = (const float*)d_in[6];
    const float* conv3_w = (const float*)d_in[7];
    const float* conv3_b = (const float*)d_in[8];
    const float* bn3_g   = (const float*)d_in[9];
    const float* bn3_b   = (const float*)d_in[10];
    float* out = (float*)d_out;

    float *buf1, *buf2, *att, *colsum, *scale, *shift;
    cudaGetSymbolAddress((void**)&buf1, g_buf1);
    cudaGetSymbolAddress((void**)&buf2, g_buf2);
    cudaGetSymbolAddress((void**)&att, g_att);
    cudaGetSymbolAddress((void**)&colsum, g_colsum);
    cudaGetSymbolAddress((void**)&scale, g_scale);
    cudaGetSymbolAddress((void**)&shift, g_shift);

    const size_t S  = (size_t)CIN * HW;     // per-batch image stride (elements)
    const size_t SA = (size_t)HW * MCB;     // per-batch attention stride

    // 1. conv1: x1 = W1 @ x + b1          -> buf1
    sgemm<false, false, true><<<dim3(HW / TILE_N, COUT / TILE_M, BB), NTHREADS>>>(
        conv1_w, x, conv1_b, buf1, COUT, HW, CIN, 0, S, S);

    // 2. att_raw[n,k] = x1^T @ centers    -> att
    sgemm<true, false, false><<<dim3(MCB / TILE_N, HW / TILE_M, BB), NTHREADS>>>(
        buf1, centers, nullptr, att, HW, MCB, COUT, S, 0, SA);

    // 3. softmax over k + column sums
    zero_colsum_kernel<<<3, 1024>>>(colsum);
    softmax_colsum_kernel<<<dim3(HW / 256, BB), 256>>>(att, colsum);

    // 4. double normalization: att /= (1e-6 + colsum)
    rcp_colsum_kernel<<<3, 1024>>>(colsum);
    scale_att_kernel<<<(unsigned)(((size_t)BB * HW * 48) / 256), 256>>>(att, colsum);

    // 5. x_re = centers @ att^T           -> buf2
    sgemm<false, true, false><<<dim3(HW / TILE_N, COUT / TILE_M, BB), NTHREADS>>>(
        centers, att, nullptr, buf2, COUT, HW, MCB, 0, SA, S);

    // 6. conv2 (no bias)                  -> buf1
    sgemm<false, false, false><<<dim3(HW / TILE_N, CIN / TILE_M, BB), NTHREADS>>>(
        conv2_w, buf2, nullptr, buf1, CIN, HW, COUT, 0, S, S);

    // 7. BN2 stats + apply (+ReLU, +residual x) -> buf2
    bn_stats_kernel<<<CIN, 256>>>(buf1, bn2_g, bn2_b, scale, shift);
    bn_apply_res_kernel<<<(unsigned)(((size_t)BB * S / 4) / 256), 256>>>(buf1, x, scale, shift, buf2);

    // 8. conv3 (+bias)                    -> buf1
    sgemm<false, false, true><<<dim3(HW / TILE_N, CIN / TILE_M, BB), NTHREADS>>>(
        conv3_w, buf2, conv3_b, buf1, CIN, HW, CIN, 0, S, S);

    // 9. BN3 stats + apply (+ReLU)        -> out
    bn_stats_kernel<<<CIN, 256>>>(buf1, bn3_g, bn3_b, scale, shift);
    bn_apply_kernel<<<(unsigned)(((size_t)BB * S / 4) / 256), 256>>>(buf1, scale, shift, out);
}

// round 3
// speedup vs baseline: 2.0271x; 2.0271x over previous
#include <cuda_runtime.h>
#include <cuda_bf16.h>
#include <math.h>
#include <stdint.h>

// ---------------- problem constants ----------------
#define BB   16
#define CIN  512
#define COUT 512
#define HW   4096
#define MCB  192
#define EPS_BN 1e-5f

// ---------------- scratch (device globals) ----------------
__device__ float g_xT  [(size_t)BB * HW * CIN];    // x transposed to [b, n, c]
__device__ float g_buf1[(size_t)BB * HW * COUT];
__device__ float g_buf2[(size_t)BB * HW * CIN];
__device__ float g_att [(size_t)BB * HW * MCB];
__device__ float g_ct  [MCB * COUT];               // centers^T [192, 512]
__device__ float g_colsum[BB * MCB];
__device__ float g_sum [CIN];
__device__ float g_sum2[CIN];
__device__ float g_scale[CIN];
__device__ float g_shift[CIN];

// ---------------- helpers ----------------
__device__ __forceinline__ uint32_t smem_u32(const void* p) {
    uint32_t a;
    asm("{ .reg .u64 t; cvta.to.shared.u64 t, %1; cvt.u32.u64 %0, t; }" : "=r"(a) : "l"(p));
    return a;
}

__device__ __forceinline__ void ldmatrix_x4(uint32_t& r0, uint32_t& r1, uint32_t& r2, uint32_t& r3, uint32_t addr) {
    asm volatile("ldmatrix.sync.aligned.m8n8.x4.shared.b16 {%0,%1,%2,%3}, [%4];"
                 : "=r"(r0), "=r"(r1), "=r"(r2), "=r"(r3) : "r"(addr));
}
__device__ __forceinline__ void ldmatrix_x2(uint32_t& r0, uint32_t& r1, uint32_t addr) {
    asm volatile("ldmatrix.sync.aligned.m8n8.x2.shared.b16 {%0,%1}, [%2];"
                 : "=r"(r0), "=r"(r1) : "r"(addr));
}
__device__ __forceinline__ void mma_bf16(float* c, uint32_t a0, uint32_t a1, uint32_t a2, uint32_t a3,
                                         uint32_t b0, uint32_t b1) {
    asm volatile("mma.sync.aligned.m16n8k16.row.col.f32.bf16.bf16.f32 "
                 "{%0,%1,%2,%3}, {%4,%5,%6,%7}, {%8,%9}, {%0,%1,%2,%3};"
                 : "+f"(c[0]), "+f"(c[1]), "+f"(c[2]), "+f"(c[3])
                 : "r"(a0), "r"(a1), "r"(a2), "r"(a3), "r"(b0), "r"(b1));
}

// pack two floats to bf16x2 (lo in low 16 bits)
__device__ __forceinline__ uint32_t pack_bf2(float x, float y) {
    __nv_bfloat162 h = __floats2bfloat162_rn(x, y);
    return *(uint32_t*)&h;
}

// ---------------- bf16x3 GEMM via mma.sync ----------------
// C[m,n] = sum_k A[m,k]*B[n,k] (+bias[n]); A: [Mtot,Kd] K-contig (batch stride aS),
// B: [Ntot,Kd] K-contig (shared across batch), C: [Mtot,Ntot] (batch stride cS).
// CTA tile: 128(M) x NT(N) x 32(K). 8 warps, warp grid 2(M) x 4(N): warp tile 64 x NT/4.
#define BK    32
#define LDK   40          // padded row length in bf16 elems (80 bytes)
#define ROWB  80          // row bytes

template<int NT, bool BIAS>
__global__ __launch_bounds__(256, 1)
void gemm_bf16x3(const float* __restrict__ Ag, const float* __restrict__ Bg,
                 const float* __restrict__ bias, float* __restrict__ Cg,
                 int Kd, int Ntot, size_t aS, size_t cS)
{
    constexpr int WN = NT / 4;          // warp n extent (32 or 24)
    constexpr int NF = WN / 8;          // n8 frags per warp (4 or 3)
    constexpr int AITERS = 4;           // 128*32/4/256
    constexpr int BITERS = NT / 32;     // NT*32/4/256
    constexpr int OFF_AH = 0;
    constexpr int OFF_AL = 128 * ROWB;            // 10240
    constexpr int OFF_BH = 2 * 128 * ROWB;        // 20480
    constexpr int OFF_BL = OFF_BH + NT * ROWB;
    constexpr int STAGE  = OFF_BL + NT * ROWB;

    extern __shared__ char dsm[];
    const uint32_t sbase = smem_u32(dsm);

    const int tid = threadIdx.x;
    const int wid = tid >> 5;
    const int lane = tid & 31;
    const int wm = wid & 1;             // 0..1
    const int wn = wid >> 1;            // 0..3
    const int m0 = blockIdx.y * 128;
    const int n0 = blockIdx.x * NT;
    const int z  = blockIdx.z;

    const float* A = Ag + (size_t)z * aS + (size_t)m0 * Kd;
    const float* B = Bg + (size_t)n0 * Kd;

    float acc[4][NF][4];
#pragma unroll
    for (int mi = 0; mi < 4; ++mi)
#pragma unroll
        for (int ni = 0; ni < NF; ++ni)
#pragma unroll
            for (int j = 0; j < 4; ++j) acc[mi][ni][j] = 0.f;

    const int NC = Kd / BK;

    float4 pa[AITERS], pb[BITERS];

    // ---- load chunk 0 ----
#pragma unroll
    for (int it = 0; it < AITERS; ++it) {
        int q = tid + it * 256;
        pa[it] = *(const float4*)(A + (size_t)(q >> 3) * Kd + (q & 7) * 4);
    }
#pragma unroll
    for (int it = 0; it < BITERS; ++it) {
        int q = tid + it * 256;
        pb[it] = *(const float4*)(B + (size_t)(q >> 3) * Kd + (q & 7) * 4);
    }

    // ---- store chunk 0 into stage 0 ----
    {
        char* st = dsm;
#pragma unroll
        for (int it = 0; it < AITERS; ++it) {
            int q = tid + it * 256;
            int row = q >> 3, c4 = q & 7;
            float4 v = pa[it];
            float hx = __bfloat162float(__float2bfloat16_rn(v.x));
            float hy = __bfloat162float(__float2bfloat16_rn(v.y));
            float hz = __bfloat162float(__float2bfloat16_rn(v.z));
            float hw = __bfloat162float(__float2bfloat16_rn(v.w));
            uint2 hi = { pack_bf2(hx, hy), pack_bf2(hz, hw) };
            uint2 lo = { pack_bf2(v.x - hx, v.y - hy), pack_bf2(v.z - hz, v.w - hw) };
            *(uint2*)(st + OFF_AH + row * ROWB + c4 * 8) = hi;
            *(uint2*)(st + OFF_AL + row * ROWB + c4 * 8) = lo;
        }
#pragma unroll
        for (int it = 0; it < BITERS; ++it) {
            int q = tid + it * 256;
            int row = q >> 3, c4 = q & 7;
            float4 v = pb[it];
            float hx = __bfloat162float(__float2bfloat16_rn(v.x));
            float hy = __bfloat162float(__float2bfloat16_rn(v.y));
            float hz = __bfloat162float(__float2bfloat16_rn(v.z));
            float hw = __bfloat162float(__float2bfloat16_rn(v.w));
            uint2 hi = { pack_bf2(hx, hy), pack_bf2(hz, hw) };
            uint2 lo = { pack_bf2(v.x - hx, v.y - hy), pack_bf2(v.z - hz, v.w - hw) };
            *(uint2*)(st + OFF_BH + row * ROWB + c4 * 8) = hi;
            *(uint2*)(st + OFF_BL + row * ROWB + c4 * 8) = lo;
        }
    }
    __syncthreads();

    for (int i = 0; i < NC; ++i) {
        // ---- prefetch chunk i+1 into registers ----
        if (i + 1 < NC) {
            const int k0 = (i + 1) * BK;
#pragma unroll
            for (int it = 0; it < AITERS; ++it) {
                int q = tid + it * 256;
                pa[it] = *(const float4*)(A + (size_t)(q >> 3) * Kd + k0 + (q & 7) * 4);
            }
#pragma unroll
            for (int it = 0; it < BITERS; ++it) {
                int q = tid + it * 256;
                pb[it] = *(const float4*)(B + (size_t)(q >> 3) * Kd + k0 + (q & 7) * 4);
            }
        }

        // ---- compute on stage i&1 ----
        {
            const uint32_t st = sbase + (i & 1) * STAGE;
            const uint32_t sAh = st + OFF_AH;
            const uint32_t sAl = st + OFF_AL;
            const uint32_t sBh = st + OFF_BH;
            const uint32_t sBl = st + OFF_BL;
            const int arow = wm * 64;
            const int brow = wn * WN;
            const int l7 = lane & 7;
            const int q  = lane >> 3;        // 0..3 (A matrices)
            const int q2 = q & 1;            // B matrix idx for lanes 0..15

#pragma unroll
            for (int k16 = 0; k16 < 2; ++k16) {
                const int kb = k16 * 32;     // byte offset of this k16 within row
                uint32_t bh[NF][2], bl[NF][2];
#pragma unroll
                for (int ni = 0; ni < NF; ++ni) {
                    uint32_t ao = (uint32_t)((brow + ni * 8 + l7) * ROWB + kb + q2 * 16);
                    ldmatrix_x2(bh[ni][0], bh[ni][1], sBh + ao);
                    ldmatrix_x2(bl[ni][0], bl[ni][1], sBl + ao);
                }
#pragma unroll
                for (int mi = 0; mi < 4; ++mi) {
                    uint32_t ao = (uint32_t)((arow + mi * 16 + (q & 1) * 8 + l7) * ROWB + kb + (q >> 1) * 16);
                    uint32_t ah0, ah1, ah2, ah3, al0, al1, al2, al3;
                    ldmatrix_x4(ah0, ah1, ah2, ah3, sAh + ao);
                    ldmatrix_x4(al0, al1, al2, al3, sAl + ao);
#pragma unroll
                    for (int ni = 0; ni < NF; ++ni) {
                        mma_bf16(acc[mi][ni], ah0, ah1, ah2, ah3, bh[ni][0], bh[ni][1]);
                        mma_bf16(acc[mi][ni], ah0, ah1, ah2, ah3, bl[ni][0], bl[ni][1]);
                        mma_bf16(acc[mi][ni], al0, al1, al2, al3, bh[ni][0], bh[ni][1]);
                    }
                }
            }
        }

        // ---- store chunk i+1 into stage (i+1)&1 ----
        if (i + 1 < NC) {
            __syncthreads();
            char* st = dsm + ((i + 1) & 1) * STAGE;
#pragma unroll
            for (int it = 0; it < AITERS; ++it) {
                int q = tid + it * 256;
                int row = q >> 3, c4 = q & 7;
                float4 v = pa[it];
                float hx = __bfloat162float(__float2bfloat16_rn(v.x));
                float hy = __bfloat162float(__float2bfloat16_rn(v.y));
                float hz = __bfloat162float(__float2bfloat16_rn(v.z));
                float hw = __bfloat162float(__float2bfloat16_rn(v.w));
                uint2 hi = { pack_bf2(hx, hy), pack_bf2(hz, hw) };
                uint2 lo = { pack_bf2(v.x - hx, v.y - hy), pack_bf2(v.z - hz, v.w - hw) };
                *(uint2*)(st + OFF_AH + row * ROWB + c4 * 8) = hi;
                *(uint2*)(st + OFF_AL + row * ROWB + c4 * 8) = lo;
            }
#pragma unroll
            for (int it = 0; it < BITERS; ++it) {
                int q = tid + it * 256;
                int row = q >> 3, c4 = q & 7;
                float4 v = pb[it];
                float hx = __bfloat162float(__float2bfloat16_rn(v.x));
                float hy = __bfloat162float(__float2bfloat16_rn(v.y));
                float hz = __bfloat162float(__float2bfloat16_rn(v.z));
                float hw = __bfloat162float(__float2bfloat16_rn(v.w));
                uint2 hi = { pack_bf2(hx, hy), pack_bf2(hz, hw) };
                uint2 lo = { pack_bf2(v.x - hx, v.y - hy), pack_bf2(v.z - hz, v.w - hw) };
                *(uint2*)(st + OFF_BH + row * ROWB + c4 * 8) = hi;
                *(uint2*)(st + OFF_BL + row * ROWB + c4 * 8) = lo;
            }
            __syncthreads();
        }
    }

    // ---- epilogue ----
    const int l4 = lane >> 2;           // 0..7
    const int lc = (lane & 3) * 2;
    float* C = Cg + (size_t)z * cS;
#pragma unroll
    for (int mi = 0; mi < 4; ++mi) {
        const int row = m0 + wm * 64 + mi * 16 + l4;
#pragma unroll
        for (int ni = 0; ni < NF; ++ni) {
            const int col = n0 + wn * WN + ni * 8 + lc;
            float b0 = BIAS ? bias[col] : 0.f;
            float b1 = BIAS ? bias[col + 1] : 0.f;
            float2 v0 = { acc[mi][ni][0] + b0, acc[mi][ni][1] + b1 };
            float2 v1 = { acc[mi][ni][2] + b0, acc[mi][ni][3] + b1 };
            *(float2*)(C + (size_t)row * Ntot + col) = v0;
            *(float2*)(C + (size_t)(row + 8) * Ntot + col) = v1;
        }
    }
}

// ---------------- transposes ----------------
__global__ void transpose_in_kernel(const float* __restrict__ in, float* __restrict__ out)
{
    __shared__ float t[32][33];
    const int b = blockIdx.z;
    const int n0 = blockIdx.x * 32, c0 = blockIdx.y * 32;
    const float* ip = in + (size_t)b * CIN * HW;
    float* op = out + (size_t)b * HW * CIN;
#pragma unroll
    for (int i = 0; i < 32; i += 8)
        t[threadIdx.y + i][threadIdx.x] = ip[(size_t)(c0 + threadIdx.y + i) * HW + n0 + threadIdx.x];
    __syncthreads();
#pragma unroll
    for (int i = 0; i < 32; i += 8)
        op[(size_t)(n0 + threadIdx.y + i) * CIN + c0 + threadIdx.x] = t[threadIdx.x][threadIdx.y + i];
}

__global__ void transpose_centers_kernel(const float* __restrict__ in, float* __restrict__ out)
{
    int idx = blockIdx.x * 256 + threadIdx.x;
    if (idx < COUT * MCB) {
        int c = idx / MCB, k = idx % MCB;
        out[k * COUT + c] = in[idx];
    }
}

__global__ void bn_apply_transpose_kernel(const float* __restrict__ in,
                                          const float* __restrict__ scale, const float* __restrict__ shift,
                                          float* __restrict__ out)
{
    __shared__ float t[32][33];
    const int b = blockIdx.z;
    const int n0 = blockIdx.x * 32, c0 = blockIdx.y * 32;
    const float* ip = in + (size_t)b * HW * CIN;
    float* op = out + (size_t)b * CIN * HW;
    const int c = c0 + threadIdx.x;
    const float sc = scale[c], sh = shift[c];
#pragma unroll
    for (int i = 0; i < 32; i += 8) {
        float v = ip[(size_t)(n0 + threadIdx.y + i) * CIN + c];
        t[threadIdx.y + i][threadIdx.x] = fmaxf(fmaf(sc, v, sh), 0.f);
    }
    __syncthreads();
#pragma unroll
    for (int i = 0; i < 32; i += 8)
        op[(size_t)(c0 + threadIdx.y + i) * HW + n0 + threadIdx.x] = t[threadIdx.x][threadIdx.y + i];
}

// ---------------- softmax + double-norm ----------------
__global__ void softmax_colsum_kernel(float* __restrict__ att, float* __restrict__ colsum)
{
    const int warp = threadIdx.x >> 5;
    const int lane = threadIdx.x & 31;
    const int b = blockIdx.y;
    const int rowBase = blockIdx.x * 256 + warp * 32;
    float cacc[6] = {0.f, 0.f, 0.f, 0.f, 0.f, 0.f};

    for (int r = 0; r < 32; ++r) {
        const int n = rowBase + r;
        float* p = att + ((size_t)b * HW + n) * MCB;
        float v[6];
        float mx = -1e30f;
#pragma unroll
        for (int j = 0; j < 6; ++j) { v[j] = p[j * 32 + lane]; mx = fmaxf(mx, v[j]); }
#pragma unroll
        for (int o = 16; o > 0; o >>= 1) mx = fmaxf(mx, __shfl_xor_sync(0xffffffffu, mx, o));
        float s = 0.f;
#pragma unroll
        for (int j = 0; j < 6; ++j) { v[j] = expf(v[j] - mx); s += v[j]; }
#pragma unroll
        for (int o = 16; o > 0; o >>= 1) s += __shfl_xor_sync(0xffffffffu, s, o);
        const float inv = 1.f / s;
#pragma unroll
        for (int j = 0; j < 6; ++j) {
            float ov = v[j] * inv;
            p[j * 32 + lane] = ov;
            cacc[j] += ov;
        }
    }
#pragma unroll
    for (int j = 0; j < 6; ++j)
        atomicAdd(&colsum[b * MCB + j * 32 + lane], cacc[j]);
}

__global__ void zero_colsum_kernel(float* cs)
{
    int i = blockIdx.x * 1024 + threadIdx.x;
    if (i < BB * MCB) cs[i] = 0.f;
}
__global__ void rcp_colsum_kernel(float* cs)
{
    int i = blockIdx.x * 1024 + threadIdx.x;
    if (i < BB * MCB) cs[i] = 1.f / (1e-6f + cs[i]);
}
__global__ void scale_att_kernel(float* __restrict__ att, const float* __restrict__ rcp)
{
    size_t i = (size_t)blockIdx.x * blockDim.x + threadIdx.x;   // float4 index
    const int k4 = (int)(i % 48);
    const size_t row = i / 48;
    const int b = (int)(row >> 12);
    float4 v = ((float4*)att)[i];
    const float4 r = ((const float4*)rcp)[b * 48 + k4];
    v.x *= r.x; v.y *= r.y; v.z *= r.z; v.w *= r.w;
    ((float4*)att)[i] = v;
}

// ---------------- BN (column stats over [rows, 512] layout) ----------------
__global__ void zero_stats_kernel(float* sum, float* sum2)
{
    int i = blockIdx.x * 512 + threadIdx.x;
    if (i < CIN) { sum[i] = 0.f; sum2[i] = 0.f; }
}
__global__ void bn_stats_cols_kernel(const float* __restrict__ t, float* __restrict__ sum, float* __restrict__ sum2)
{
    const int c = threadIdx.x;           // 512 threads
    const size_t r0 = (size_t)blockIdx.x * 256;
    const float* p = t + r0 * CIN + c;
    float s = 0.f, s2 = 0.f;
    for (int r = 0; r < 256; ++r) {
        float v = p[(size_t)r * CIN];
        s += v; s2 += v * v;
    }
    atomicAdd(&sum[c], s);
    atomicAdd(&sum2[c], s2);
}
__global__ void bn_finalize_kernel(const float* __restrict__ sum, const float* __restrict__ sum2,
                                   const float* __restrict__ gamma, const float* __restrict__ beta,
                                   float* __restrict__ scale, float* __restrict__ shift)
{
    int c = threadIdx.x;
    const float N = (float)((size_t)BB * HW);
    float mean = sum[c] / N;
    float var = sum2[c] / N - mean * mean;
    float sc = gamma[c] * rsqrtf(var + EPS_BN);
    scale[c] = sc;
    shift[c] = beta[c] - mean * sc;
}
__global__ void bn_apply_res_kernel(const float* __restrict__ t, const float* __restrict__ xT,
                                    const float* __restrict__ scale, const float* __restrict__ shift,
                                    float* __restrict__ out)
{
    size_t i = (size_t)blockIdx.x * blockDim.x + threadIdx.x;   // float4 index
    const int c4 = (int)(i & 127);
    const float4 sc = ((const float4*)scale)[c4];
    const float4 sh = ((const float4*)shift)[c4];
    float4 v = ((const float4*)t)[i];
    float4 xv = ((const float4*)xT)[i];
    v.x = fmaxf(fmaf(sc.x, v.x, sh.x), 0.f) + xv.x;
    v.y = fmaxf(fmaf(sc.y, v.y, sh.y), 0.f) + xv.y;
    v.z = fmaxf(fmaf(sc.z, v.z, sh.z), 0.f) + xv.z;
    v.w = fmaxf(fmaf(sc.w, v.w, sh.w), 0.f) + xv.w;
    ((float4*)out)[i] = v;
}

// ---------------- launch ----------------
extern "C" void kernel_launch(void* const* d_in, const int* in_sizes, int n_in,
                              void* d_out, int out_size)
{
    const float* x       = (const float*)d_in[0];
    const float* centers = (const float*)d_in[1];
    const float* conv1_w = (const float*)d_in[2];
    const float* conv1_b = (const float*)d_in[3];
    const float* conv2_w = (const float*)d_in[4];
    const float* bn2_g   = (const float*)d_in[5];
    const float* bn2_b   = (const float*)d_in[6];
    const float* conv3_w = (const float*)d_in[7];
    const float* conv3_b = (const float*)d_in[8];
    const float* bn3_g   = (const float*)d_in[9];
    const float* bn3_b   = (const float*)d_in[10];
    float* out = (float*)d_out;

    float *xT, *buf1, *buf2, *att, *ct, *colsum, *sum, *sum2, *scale, *shift;
    cudaGetSymbolAddress((void**)&xT, g_xT);
    cudaGetSymbolAddress((void**)&buf1, g_buf1);
    cudaGetSymbolAddress((void**)&buf2, g_buf2);
    cudaGetSymbolAddress((void**)&att, g_att);
    cudaGetSymbolAddress((void**)&ct, g_ct);
    cudaGetSymbolAddress((void**)&colsum, g_colsum);
    cudaGetSymbolAddress((void**)&sum, g_sum);
    cudaGetSymbolAddress((void**)&sum2, g_sum2);
    cudaGetSymbolAddress((void**)&scale, g_scale);
    cudaGetSymbolAddress((void**)&shift, g_shift);

    const size_t S  = (size_t)HW * CIN;
    const size_t SA = (size_t)HW * MCB;

    // dynamic smem: 2 stages of (A 128 + B NT) rows * 80B * 2 (hi+lo)
    const int SM128 = 2 * (2 * 128 * 80 + 2 * 128 * 80);   // 81920
    const int SM96  = 2 * (2 * 128 * 80 + 2 * 96 * 80);    // 71680
    cudaFuncSetAttribute(gemm_bf16x3<128, true>,  cudaFuncAttributeMaxDynamicSharedMemorySize, SM128);
    cudaFuncSetAttribute(gemm_bf16x3<128, false>, cudaFuncAttributeMaxDynamicSharedMemorySize, SM128);
    cudaFuncSetAttribute(gemm_bf16x3<96,  false>, cudaFuncAttributeMaxDynamicSharedMemorySize, SM96);

    // 0. layout changes
    transpose_in_kernel<<<dim3(HW / 32, CIN / 32, BB), dim3(32, 8)>>>(x, xT);
    transpose_centers_kernel<<<(COUT * MCB + 255) / 256, 256>>>(centers, ct);

    // 1. conv1: buf1[n, co] = xT @ W1^T + b1
    gemm_bf16x3<128, true><<<dim3(4, 32, BB), 256, SM128>>>(
        xT, conv1_w, conv1_b, buf1, CIN, COUT, S, S);

    // 2. att[n, k] = buf1 @ ct^T
    gemm_bf16x3<96, false><<<dim3(2, 32, BB), 256, SM96>>>(
        buf1, ct, nullptr, att, COUT, MCB, S, SA);

    // 3. softmax + double normalization
    zero_colsum_kernel<<<3, 1024>>>(colsum);
    softmax_colsum_kernel<<<dim3(HW / 256, BB), 256>>>(att, colsum);
    rcp_colsum_kernel<<<3, 1024>>>(colsum);
    scale_att_kernel<<<(unsigned)(((size_t)BB * HW * 48) / 256), 256>>>(att, colsum);

    // 4. recon: buf2[n, c] = att @ centers^T
    gemm_bf16x3<128, false><<<dim3(4, 32, BB), 256, SM128>>>(
        att, centers, nullptr, buf2, MCB, COUT, SA, S);

    // 5. conv2 (no bias) -> buf1
    gemm_bf16x3<128, false><<<dim3(4, 32, BB), 256, SM128>>>(
        buf2, conv2_w, nullptr, buf1, COUT, CIN, S, S);

    // 6. BN2 + ReLU + residual -> buf2
    zero_stats_kernel<<<1, 512>>>(sum, sum2);
    bn_stats_cols_kernel<<<256, 512>>>(buf1, sum, sum2);
    bn_finalize_kernel<<<1, 512>>>(sum, sum2, bn2_g, bn2_b, scale, shift);
    bn_apply_res_kernel<<<(unsigned)(((size_t)BB * S / 4) / 256), 256>>>(buf1, xT, scale, shift, buf2);

    // 7. conv3 (+bias) -> buf1
    gemm_bf16x3<128, true><<<dim3(4, 32, BB), 256, SM128>>>(
        buf2, conv3_w, conv3_b, buf1, CIN, CIN, S, S);

    // 8. BN3 + ReLU + transpose back -> out
    zero_stats_kernel<<<1, 512>>>(sum, sum2);
    bn_stats_cols_kernel<<<256, 512>>>(buf1, sum, sum2);
    bn_finalize_kernel<<<1, 512>>>(sum, sum2, bn3_g, bn3_b, scale, shift);
    bn_apply_transpose_kernel<<<dim3(HW / 32, CIN / 32, BB), dim3(32, 8)>>>(buf1, scale, shift, out);
}

// round 4
// speedup vs baseline: 2.1268x; 1.0492x over previous
#include <cuda_runtime.h>
#include <cuda_bf16.h>
#include <math.h>
#include <stdint.h>

// ---------------- problem constants ----------------
#define BB   16
#define CIN  512
#define COUT 512
#define HW   4096
#define MCB  192
#define EPS_BN 1e-5f
#define BK   32
#define ROWB 80

typedef __nv_bfloat16 bf16;

// ---------------- scratch (device globals) ----------------
__device__ bf16  g_xT_h [(size_t)BB * HW * CIN];
__device__ bf16  g_xT_l [(size_t)BB * HW * CIN];
__device__ bf16  g_b1_h [(size_t)BB * HW * COUT];
__device__ bf16  g_b1_l [(size_t)BB * HW * COUT];
__device__ bf16  g_b2_h [(size_t)BB * HW * CIN];
__device__ bf16  g_b2_l [(size_t)BB * HW * CIN];
__device__ float g_buf1 [(size_t)BB * HW * COUT];
__device__ float g_att  [(size_t)BB * HW * MCB];
__device__ bf16  g_att_h[(size_t)BB * HW * MCB];
__device__ bf16  g_att_l[(size_t)BB * HW * MCB];
__device__ bf16  g_ct_h [MCB * COUT];
__device__ bf16  g_ct_l [MCB * COUT];
__device__ bf16  g_c_h  [COUT * MCB];
__device__ bf16  g_c_l  [COUT * MCB];
__device__ bf16  g_w1_h [COUT * CIN];
__device__ bf16  g_w1_l [COUT * CIN];
__device__ bf16  g_w2_h [CIN * COUT];
__device__ bf16  g_w2_l [CIN * COUT];
__device__ bf16  g_w3_h [CIN * CIN];
__device__ bf16  g_w3_l [CIN * CIN];
__device__ float g_colsum[BB * MCB];
__device__ float g_sum [CIN];
__device__ float g_sum2[CIN];
__device__ float g_scale[CIN];
__device__ float g_shift[CIN];

// ---------------- helpers ----------------
__device__ __forceinline__ uint32_t smem_u32(const void* p) {
    uint32_t a;
    asm("{ .reg .u64 t; cvta.to.shared.u64 t, %1; cvt.u32.u64 %0, t; }" : "=r"(a) : "l"(p));
    return a;
}
__device__ __forceinline__ void cp16(uint32_t dst, const void* src) {
    asm volatile("cp.async.cg.shared.global [%0], [%1], 16;" :: "r"(dst), "l"(src));
}
__device__ __forceinline__ void cp_commit() {
    asm volatile("cp.async.commit_group;" ::: "memory");
}
__device__ __forceinline__ void cp_wait1() {
    asm volatile("cp.async.wait_group 1;" ::: "memory");
}
__device__ __forceinline__ void ldmatrix_x4(uint32_t& r0, uint32_t& r1, uint32_t& r2, uint32_t& r3, uint32_t addr) {
    asm volatile("ldmatrix.sync.aligned.m8n8.x4.shared.b16 {%0,%1,%2,%3}, [%4];"
                 : "=r"(r0), "=r"(r1), "=r"(r2), "=r"(r3) : "r"(addr));
}
__device__ __forceinline__ void ldmatrix_x2(uint32_t& r0, uint32_t& r1, uint32_t addr) {
    asm volatile("ldmatrix.sync.aligned.m8n8.x2.shared.b16 {%0,%1}, [%2];"
                 : "=r"(r0), "=r"(r1) : "r"(addr));
}
__device__ __forceinline__ void mma_bf16(float* c, uint32_t a0, uint32_t a1, uint32_t a2, uint32_t a3,
                                         uint32_t b0, uint32_t b1) {
    asm volatile("mma.sync.aligned.m16n8k16.row.col.f32.bf16.bf16.f32 "
                 "{%0,%1,%2,%3}, {%4,%5,%6,%7}, {%8,%9}, {%0,%1,%2,%3};"
                 : "+f"(c[0]), "+f"(c[1]), "+f"(c[2]), "+f"(c[3])
                 : "r"(a0), "r"(a1), "r"(a2), "r"(a3), "r"(b0), "r"(b1));
}
__device__ __forceinline__ uint32_t pack_bf2(float x, float y) {
    __nv_bfloat162 h = __floats2bfloat162_rn(x, y);
    return *(uint32_t*)&h;
}
__device__ __forceinline__ void split1(float v, bf16& h, bf16& l) {
    h = __float2bfloat16_rn(v);
    l = __float2bfloat16_rn(v - __bfloat162float(h));
}

// ---------------- split bf16x3 GEMM with cp.async pipeline ----------------
// C[m,n] = sum_k A[m,k]*B[n,k] (+bias[n]).
// A = (Ah, Al) bf16 planes [Mtot,Kd] K-contig, batch stride aS (elements).
// B = (Bh, Bl) bf16 planes [Ntot,Kd] K-contig, shared across batch.
// Output: fp32 Cf, or split planes (Ch, Cl), batch stride cS.
// CTA tile 128 x NT x 32; 8 warps (2 x 4), warp tile 64 x NT/4.
template<int NT, bool BIAS, bool SPLIT_OUT>
__global__ __launch_bounds__(256, 2)
void gemm_sp(const bf16* __restrict__ Ahg, const bf16* __restrict__ Alg,
             const bf16* __restrict__ Bhg, const bf16* __restrict__ Blg,
             const float* __restrict__ bias,
             float* __restrict__ Cf, bf16* __restrict__ Chp, bf16* __restrict__ Clp,
             int Kd, int Ntot, size_t aS, size_t cS)
{
    constexpr int WN = NT / 4;
    constexpr int NF = WN / 8;
    constexpr int OFF_AL = 128 * ROWB;            // 10240
    constexpr int OFF_BH = 2 * 128 * ROWB;        // 20480
    constexpr int STAGE  = OFF_BH + 2 * NT * ROWB;

    extern __shared__ char dsm[];
    const uint32_t sbase = smem_u32(dsm);

    const int tid = threadIdx.x;
    const int lane = tid & 31;
    const int wid = tid >> 5;
    const int wm = wid & 1;
    const int wn = wid >> 1;
    const int m0 = blockIdx.y * 128;
    const int n0 = blockIdx.x * NT;
    const int z  = blockIdx.z;

    const bf16* Ah = Ahg + (size_t)z * aS + (size_t)m0 * Kd;
    const bf16* Al = Alg + (size_t)z * aS + (size_t)m0 * Kd;
    const bf16* Bh = Bhg + (size_t)n0 * Kd;
    const bf16* Bl = Blg + (size_t)n0 * Kd;

    const int NC = Kd / BK;

    float acc[4][NF][4];
#pragma unroll
    for (int mi = 0; mi < 4; ++mi)
#pragma unroll
        for (int ni = 0; ni < NF; ++ni)
#pragma unroll
            for (int j = 0; j < 4; ++j) acc[mi][ni][j] = 0.f;

    auto load_stage = [&](int i) {
        if (i < NC) {
            const uint32_t st = sbase + (i & 1) * STAGE;
            const int k0 = i * BK;
#pragma unroll
            for (int it = 0; it < 2; ++it) {
                int q = tid + it * 256;
                int row = q >> 2, ch = q & 3;
                uint32_t d = st + row * ROWB + ch * 16;
                size_t so = (size_t)row * Kd + k0 + ch * 8;
                cp16(d, Ah + so);
                cp16(d + OFF_AL, Al + so);
            }
            for (int q = tid; q < NT * 4; q += 256) {
                int row = q >> 2, ch = q & 3;
                uint32_t d = st + OFF_BH + row * ROWB + ch * 16;
                size_t so = (size_t)row * Kd + k0 + ch * 8;
                cp16(d, Bh + so);
                cp16(d + NT * ROWB, Bl + so);
            }
        }
        cp_commit();
    };

    load_stage(0);
    load_stage(1);

    const int arow = wm * 64;
    const int brow = wn * WN;
    const int l7 = lane & 7;
    const int q  = lane >> 3;
    const int q2 = q & 1;

    for (int i = 0; i < NC; ++i) {
        cp_wait1();
        __syncthreads();

        const uint32_t st = sbase + (i & 1) * STAGE;
        const uint32_t sAh = st;
        const uint32_t sAl = st + OFF_AL;
        const uint32_t sBh = st + OFF_BH;
        const uint32_t sBl = st + OFF_BH + NT * ROWB;

#pragma unroll
        for (int k16 = 0; k16 < 2; ++k16) {
            const int kb = k16 * 32;
            uint32_t bh[NF][2], bl[NF][2];
#pragma unroll
            for (int ni = 0; ni < NF; ++ni) {
                uint32_t ao = (uint32_t)((brow + ni * 8 + l7) * ROWB + kb + q2 * 16);
                ldmatrix_x2(bh[ni][0], bh[ni][1], sBh + ao);
                ldmatrix_x2(bl[ni][0], bl[ni][1], sBl + ao);
            }
#pragma unroll
            for (int mi = 0; mi < 4; ++mi) {
                uint32_t ao = (uint32_t)((arow + mi * 16 + (q & 1) * 8 + l7) * ROWB + kb + (q >> 1) * 16);
                uint32_t ah0, ah1, ah2, ah3, al0, al1, al2, al3;
                ldmatrix_x4(ah0, ah1, ah2, ah3, sAh + ao);
                ldmatrix_x4(al0, al1, al2, al3, sAl + ao);
#pragma unroll
                for (int ni = 0; ni < NF; ++ni) {
                    mma_bf16(acc[mi][ni], ah0, ah1, ah2, ah3, bh[ni][0], bh[ni][1]);
                    mma_bf16(acc[mi][ni], ah0, ah1, ah2, ah3, bl[ni][0], bl[ni][1]);
                    mma_bf16(acc[mi][ni], al0, al1, al2, al3, bh[ni][0], bh[ni][1]);
                }
            }
        }
        __syncthreads();
        load_stage(i + 2);
    }

    // ---- epilogue ----
    const int l4 = lane >> 2;
    const int lc = (lane & 3) * 2;
#pragma unroll
    for (int mi = 0; mi < 4; ++mi) {
        const int row = m0 + wm * 64 + mi * 16 + l4;
#pragma unroll
        for (int ni = 0; ni < NF; ++ni) {
            const int col = n0 + wn * WN + ni * 8 + lc;
            float b0 = BIAS ? bias[col] : 0.f;
            float b1 = BIAS ? bias[col + 1] : 0.f;
            float v00 = acc[mi][ni][0] + b0, v01 = acc[mi][ni][1] + b1;
            float v10 = acc[mi][ni][2] + b0, v11 = acc[mi][ni][3] + b1;
            if (SPLIT_OUT) {
                bf16 h0, l0, h1, l1;
                size_t o0 = (size_t)z * cS + (size_t)row * Ntot + col;
                size_t o1 = (size_t)z * cS + (size_t)(row + 8) * Ntot + col;
                split1(v00, h0, l0); split1(v01, h1, l1);
                *(uint32_t*)(Chp + o0) = pack_bf2(__bfloat162float(h0), __bfloat162float(h1));
                *(uint32_t*)(Clp + o0) = pack_bf2(__bfloat162float(l0), __bfloat162float(l1));
                split1(v10, h0, l0); split1(v11, h1, l1);
                *(uint32_t*)(Chp + o1) = pack_bf2(__bfloat162float(h0), __bfloat162float(h1));
                *(uint32_t*)(Clp + o1) = pack_bf2(__bfloat162float(l0), __bfloat162float(l1));
            } else {
                float* C = Cf + (size_t)z * cS;
                float2 w0 = { v00, v01 };
                float2 w1 = { v10, v11 };
                *(float2*)(C + (size_t)row * Ntot + col) = w0;
                *(float2*)(C + (size_t)(row + 8) * Ntot + col) = w1;
            }
        }
    }
}

// ---------------- prep kernels ----------------
__global__ void split_kernel(const float* __restrict__ in, bf16* __restrict__ h, bf16* __restrict__ l, int n)
{
    int i = blockIdx.x * 256 + threadIdx.x;
    if (i < n) {
        float v = in[i];
        bf16 hh, ll;
        split1(v, hh, ll);
        h[i] = hh; l[i] = ll;
    }
}

// x [b, C, HW] -> split planes xT [b, HW, C]
__global__ void transpose_in_split(const float* __restrict__ in, bf16* __restrict__ oh, bf16* __restrict__ ol)
{
    __shared__ float t[32][33];
    const int b = blockIdx.z;
    const int n0 = blockIdx.x * 32, c0 = blockIdx.y * 32;
    const float* ip = in + (size_t)b * CIN * HW;
#pragma unroll
    for (int i = 0; i < 32; i += 8)
        t[threadIdx.y + i][threadIdx.x] = ip[(size_t)(c0 + threadIdx.y + i) * HW + n0 + threadIdx.x];
    __syncthreads();
#pragma unroll
    for (int i = 0; i < 32; i += 8) {
        float v = t[threadIdx.x][threadIdx.y + i];
        bf16 hh, ll;
        split1(v, hh, ll);
        size_t o = (size_t)b * HW * CIN + (size_t)(n0 + threadIdx.y + i) * CIN + c0 + threadIdx.x;
        oh[o] = hh; ol[o] = ll;
    }
}

// centers [512, 192] -> split ct [192, 512]
__global__ void transpose_centers_split(const float* __restrict__ in, bf16* __restrict__ oh, bf16* __restrict__ ol)
{
    int idx = blockIdx.x * 256 + threadIdx.x;
    if (idx < COUT * MCB) {
        int c = idx / MCB, k = idx % MCB;
        bf16 hh, ll;
        split1(in[idx], hh, ll);
        oh[k * COUT + c] = hh;
        ol[k * COUT + c] = ll;
    }
}

// ---------------- softmax + double-norm ----------------
__global__ void softmax_colsum_kernel(float* __restrict__ att, float* __restrict__ colsum)
{
    const int warp = threadIdx.x >> 5;
    const int lane = threadIdx.x & 31;
    const int b = blockIdx.y;
    const int rowBase = blockIdx.x * 256 + warp * 32;
    float cacc[6] = {0.f, 0.f, 0.f, 0.f, 0.f, 0.f};

    for (int r = 0; r < 32; ++r) {
        const int n = rowBase + r;
        float* p = att + ((size_t)b * HW + n) * MCB;
        float v[6];
        float mx = -1e30f;
#pragma unroll
        for (int j = 0; j < 6; ++j) { v[j] = p[j * 32 + lane]; mx = fmaxf(mx, v[j]); }
#pragma unroll
        for (int o = 16; o > 0; o >>= 1) mx = fmaxf(mx, __shfl_xor_sync(0xffffffffu, mx, o));
        float s = 0.f;
#pragma unroll
        for (int j = 0; j < 6; ++j) { v[j] = expf(v[j] - mx); s += v[j]; }
#pragma unroll
        for (int o = 16; o > 0; o >>= 1) s += __shfl_xor_sync(0xffffffffu, s, o);
        const float inv = 1.f / s;
#pragma unroll
        for (int j = 0; j < 6; ++j) {
            float ov = v[j] * inv;
            p[j * 32 + lane] = ov;
            cacc[j] += ov;
        }
    }
#pragma unroll
    for (int j = 0; j < 6; ++j)
        atomicAdd(&colsum[b * MCB + j * 32 + lane], cacc[j]);
}

__global__ void zero_colsum_kernel(float* cs)
{
    int i = blockIdx.x * 1024 + threadIdx.x;
    if (i < BB * MCB) cs[i] = 0.f;
}
__global__ void rcp_colsum_kernel(float* cs)
{
    int i = blockIdx.x * 1024 + threadIdx.x;
    if (i < BB * MCB) cs[i] = 1.f / (1e-6f + cs[i]);
}
// att fp32 * rcp -> split planes
__global__ void scale_att_split(const float* __restrict__ att, const float* __restrict__ rcp,
                                bf16* __restrict__ oh, bf16* __restrict__ ol)
{
    size_t i = (size_t)blockIdx.x * blockDim.x + threadIdx.x;   // float4 index
    const int k4 = (int)(i % 48);
    const size_t row = i / 48;
    const int b = (int)(row >> 12);
    float4 v = ((const float4*)att)[i];
    const float4 r = ((const float4*)rcp)[b * 48 + k4];
    v.x *= r.x; v.y *= r.y; v.z *= r.z; v.w *= r.w;
    bf16 hx, lx, hy, ly, hz, lz, hw, lw;
    split1(v.x, hx, lx); split1(v.y, hy, ly); split1(v.z, hz, lz); split1(v.w, hw, lw);
    uint2 ho = { pack_bf2(__bfloat162float(hx), __bfloat162float(hy)),
                 pack_bf2(__bfloat162float(hz), __bfloat162float(hw)) };
    uint2 lo = { pack_bf2(__bfloat162float(lx), __bfloat162float(ly)),
                 pack_bf2(__bfloat162float(lz), __bfloat162float(lw)) };
    *(uint2*)(oh + i * 4) = ho;
    *(uint2*)(ol + i * 4) = lo;
}

// ---------------- BN ----------------
__global__ void zero_stats_kernel(float* sum, float* sum2)
{
    int i = blockIdx.x * 512 + threadIdx.x;
    if (i < CIN) { sum[i] = 0.f; sum2[i] = 0.f; }
}
__global__ void bn_stats_cols_kernel(const float* __restrict__ t, float* __restrict__ sum, float* __restrict__ sum2)
{
    const int c = threadIdx.x;
    const size_t r0 = (size_t)blockIdx.x * 256;
    const float* p = t + r0 * CIN + c;
    float s = 0.f, s2 = 0.f;
    for (int r = 0; r < 256; ++r) {
        float v = p[(size_t)r * CIN];
        s += v; s2 += v * v;
    }
    atomicAdd(&sum[c], s);
    atomicAdd(&sum2[c], s2);
}
__global__ void bn_finalize_kernel(const float* __restrict__ sum, const float* __restrict__ sum2,
                                   const float* __restrict__ gamma, const float* __restrict__ beta,
                                   float* __restrict__ scale, float* __restrict__ shift)
{
    int c = threadIdx.x;
    const float N = (float)((size_t)BB * HW);
    float mean = sum[c] / N;
    float var = sum2[c] / N - mean * mean;
    float sc = gamma[c] * rsqrtf(var + EPS_BN);
    scale[c] = sc;
    shift[c] = beta[c] - mean * sc;
}
// relu(sc*t + sh) + (xh + xl)  -> split planes
__global__ void bn_apply_res_split(const float* __restrict__ t,
                                   const bf16* __restrict__ xh, const bf16* __restrict__ xl,
                                   const float* __restrict__ scale, const float* __restrict__ shift,
                                   bf16* __restrict__ oh, bf16* __restrict__ ol)
{
    size_t i = (size_t)blockIdx.x * blockDim.x + threadIdx.x;   // float4 index
    const int c4 = (int)(i & 127);
    const float4 sc = ((const float4*)scale)[c4];
    const float4 sh = ((const float4*)shift)[c4];
    float4 v = ((const float4*)t)[i];
    uint2 xhu = *(const uint2*)(xh + i * 4);
    uint2 xlu = *(const uint2*)(xl + i * 4);
    __nv_bfloat162 xh0 = *(__nv_bfloat162*)&xhu.x;
    __nv_bfloat162 xh1 = *(__nv_bfloat162*)&xhu.y;
    __nv_bfloat162 xl0 = *(__nv_bfloat162*)&xlu.x;
    __nv_bfloat162 xl1 = *(__nv_bfloat162*)&xlu.y;
    v.x = fmaxf(fmaf(sc.x, v.x, sh.x), 0.f) + __bfloat162float(xh0.x) + __bfloat162float(xl0.x);
    v.y = fmaxf(fmaf(sc.y, v.y, sh.y), 0.f) + __bfloat162float(xh0.y) + __bfloat162float(xl0.y);
    v.z = fmaxf(fmaf(sc.z, v.z, sh.z), 0.f) + __bfloat162float(xh1.x) + __bfloat162float(xl1.x);
    v.w = fmaxf(fmaf(sc.w, v.w, sh.w), 0.f) + __bfloat162float(xh1.y) + __bfloat162float(xl1.y);
    bf16 hx, lx, hy, ly, hz, lz, hw, lw;
    split1(v.x, hx, lx); split1(v.y, hy, ly); split1(v.z, hz, lz); split1(v.w, hw, lw);
    uint2 ho = { pack_bf2(__bfloat162float(hx), __bfloat162float(hy)),
                 pack_bf2(__bfloat162float(hz), __bfloat162float(hw)) };
    uint2 lo = { pack_bf2(__bfloat162float(lx), __bfloat162float(ly)),
                 pack_bf2(__bfloat162float(lz), __bfloat162float(lw)) };
    *(uint2*)(oh + i * 4) = ho;
    *(uint2*)(ol + i * 4) = lo;
}

// buf [b, HW, C] -> out [b, C, HW] with BN+ReLU
__global__ void bn_apply_transpose_kernel(const float* __restrict__ in,
                                          const float* __restrict__ scale, const float* __restrict__ shift,
                                          float* __restrict__ out)
{
    __shared__ float t[32][33];
    const int b = blockIdx.z;
    const int n0 = blockIdx.x * 32, c0 = blockIdx.y * 32;
    const float* ip = in + (size_t)b * HW * CIN;
    float* op = out + (size_t)b * CIN * HW;
    const int c = c0 + threadIdx.x;
    const float sc = scale[c], sh = shift[c];
#pragma unroll
    for (int i = 0; i < 32; i += 8) {
        float v = ip[(size_t)(n0 + threadIdx.y + i) * CIN + c];
        t[threadIdx.y + i][threadIdx.x] = fmaxf(fmaf(sc, v, sh), 0.f);
    }
    __syncthreads();
#pragma unroll
    for (int i = 0; i < 32; i += 8)
        op[(size_t)(c0 + threadIdx.y + i) * HW + n0 + threadIdx.x] = t[threadIdx.x][threadIdx.y + i];
}

// ---------------- launch ----------------
extern "C" void kernel_launch(void* const* d_in, const int* in_sizes, int n_in,
                              void* d_out, int out_size)
{
    const float* x       = (const float*)d_in[0];
    const float* centers = (const float*)d_in[1];
    const float* conv1_w = (const float*)d_in[2];
    const float* conv1_b = (const float*)d_in[3];
    const float* conv2_w = (const float*)d_in[4];
    const float* bn2_g   = (const float*)d_in[5];
    const float* bn2_b   = (const float*)d_in[6];
    const float* conv3_w = (const float*)d_in[7];
    const float* conv3_b = (const float*)d_in[8];
    const float* bn3_g   = (const float*)d_in[9];
    const float* bn3_b   = (const float*)d_in[10];
    float* out = (float*)d_out;

    bf16 *xTh, *xTl, *b1h, *b1l, *b2h, *b2l, *atth, *attl, *cth, *ctl, *ch, *cl;
    bf16 *w1h, *w1l, *w2h, *w2l, *w3h, *w3l;
    float *buf1, *att, *colsum, *sum, *sum2, *scale, *shift;
    cudaGetSymbolAddress((void**)&xTh, g_xT_h);  cudaGetSymbolAddress((void**)&xTl, g_xT_l);
    cudaGetSymbolAddress((void**)&b1h, g_b1_h);  cudaGetSymbolAddress((void**)&b1l, g_b1_l);
    cudaGetSymbolAddress((void**)&b2h, g_b2_h);  cudaGetSymbolAddress((void**)&b2l, g_b2_l);
    cudaGetSymbolAddress((void**)&atth, g_att_h); cudaGetSymbolAddress((void**)&attl, g_att_l);
    cudaGetSymbolAddress((void**)&cth, g_ct_h);  cudaGetSymbolAddress((void**)&ctl, g_ct_l);
    cudaGetSymbolAddress((void**)&ch, g_c_h);    cudaGetSymbolAddress((void**)&cl, g_c_l);
    cudaGetSymbolAddress((void**)&w1h, g_w1_h);  cudaGetSymbolAddress((void**)&w1l, g_w1_l);
    cudaGetSymbolAddress((void**)&w2h, g_w2_h);  cudaGetSymbolAddress((void**)&w2l, g_w2_l);
    cudaGetSymbolAddress((void**)&w3h, g_w3_h);  cudaGetSymbolAddress((void**)&w3l, g_w3_l);
    cudaGetSymbolAddress((void**)&buf1, g_buf1);
    cudaGetSymbolAddress((void**)&att, g_att);
    cudaGetSymbolAddress((void**)&colsum, g_colsum);
    cudaGetSymbolAddress((void**)&sum, g_sum);
    cudaGetSymbolAddress((void**)&sum2, g_sum2);
    cudaGetSymbolAddress((void**)&scale, g_scale);
    cudaGetSymbolAddress((void**)&shift, g_shift);

    const size_t S  = (size_t)HW * CIN;
    const size_t SA = (size_t)HW * MCB;

    const int SM128 = 2 * (20480 + 2 * 128 * ROWB);   // 81920
    const int SM96  = 2 * (20480 + 2 * 96 * ROWB);    // 71680
    cudaFuncSetAttribute(gemm_sp<128, true,  true >, cudaFuncAttributeMaxDynamicSharedMemorySize, SM128);
    cudaFuncSetAttribute(gemm_sp<96,  false, false>, cudaFuncAttributeMaxDynamicSharedMemorySize, SM96);
    cudaFuncSetAttribute(gemm_sp<128, false, true >, cudaFuncAttributeMaxDynamicSharedMemorySize, SM128);
    cudaFuncSetAttribute(gemm_sp<128, false, false>, cudaFuncAttributeMaxDynamicSharedMemorySize, SM128);
    cudaFuncSetAttribute(gemm_sp<128, true,  false>, cudaFuncAttributeMaxDynamicSharedMemorySize, SM128);

    // 0. prep: transpose + split everything
    transpose_in_split<<<dim3(HW / 32, CIN / 32, BB), dim3(32, 8)>>>(x, xTh, xTl);
    transpose_centers_split<<<(COUT * MCB + 255) / 256, 256>>>(centers, cth, ctl);
    split_kernel<<<(COUT * MCB + 255) / 256, 256>>>(centers, ch, cl, COUT * MCB);
    split_kernel<<<(COUT * CIN + 255) / 256, 256>>>(conv1_w, w1h, w1l, COUT * CIN);
    split_kernel<<<(CIN * COUT + 255) / 256, 256>>>(conv2_w, w2h, w2l, CIN * COUT);
    split_kernel<<<(CIN * CIN + 255) / 256, 256>>>(conv3_w, w3h, w3l, CIN * CIN);

    // 1. conv1 -> split buf1 planes
    gemm_sp<128, true, true><<<dim3(4, 32, BB), 256, SM128>>>(
        xTh, xTl, w1h, w1l, conv1_b, nullptr, b1h, b1l, CIN, COUT, S, S);

    // 2. att = buf1 @ ct^T -> fp32 att
    gemm_sp<96, false, false><<<dim3(2, 32, BB), 256, SM96>>>(
        b1h, b1l, cth, ctl, nullptr, att, nullptr, nullptr, COUT, MCB, S, SA);

    // 3. softmax + double normalization (+ split att)
    zero_colsum_kernel<<<3, 1024>>>(colsum);
    softmax_colsum_kernel<<<dim3(HW / 256, BB), 256>>>(att, colsum);
    rcp_colsum_kernel<<<3, 1024>>>(colsum);
    scale_att_split<<<(unsigned)(((size_t)BB * HW * 48) / 256), 256>>>(att, colsum, atth, attl);

    // 4. recon = att @ centers^T -> split buf2 planes
    gemm_sp<128, false, true><<<dim3(4, 32, BB), 256, SM128>>>(
        atth, attl, ch, cl, nullptr, nullptr, b2h, b2l, MCB, COUT, SA, S);

    // 5. conv2 -> fp32 buf1
    gemm_sp<128, false, false><<<dim3(4, 32, BB), 256, SM128>>>(
        b2h, b2l, w2h, w2l, nullptr, buf1, nullptr, nullptr, COUT, CIN, S, S);

    // 6. BN2 + ReLU + residual -> split buf2 planes
    zero_stats_kernel<<<1, 512>>>(sum, sum2);
    bn_stats_cols_kernel<<<256, 512>>>(buf1, sum, sum2);
    bn_finalize_kernel<<<1, 512>>>(sum, sum2, bn2_g, bn2_b, scale, shift);
    bn_apply_res_split<<<(unsigned)(((size_t)BB * S / 4) / 256), 256>>>(buf1, xTh, xTl, scale, shift, b2h, b2l);

    // 7. conv3 -> fp32 buf1
    gemm_sp<128, true, false><<<dim3(4, 32, BB), 256, SM128>>>(
        b2h, b2l, w3h, w3l, conv3_b, buf1, nullptr, nullptr, CIN, CIN, S, S);

    // 8. BN3 + ReLU + transpose -> out
    zero_stats_kernel<<<1, 512>>>(sum, sum2);
    bn_stats_cols_kernel<<<256, 512>>>(buf1, sum, sum2);
    bn_finalize_kernel<<<1, 512>>>(sum, sum2, bn3_g, bn3_b, scale, shift);
    bn_apply_transpose_kernel<<<dim3(HW / 32, CIN / 32, BB), dim3(32, 8)>>>(buf1, scale, shift, out);
}

// round 5
// speedup vs baseline: 2.3881x; 1.1229x over previous
#include <cuda_runtime.h>
#include <cuda_bf16.h>
#include <math.h>
#include <stdint.h>

// ---------------- problem constants ----------------
#define BB   16
#define CIN  512
#define COUT 512
#define HW   4096
#define MCB  192
#define EPS_BN 1e-5f
#define BK   32          // K elements per chunk (= 64 bytes bf16)

typedef __nv_bfloat16 bf16;

// SW64 swizzle on byte offsets (64B rows, conflict-free for ldmatrix)
#define SWZ(o) ((o) ^ (((o) >> 3) & 0x30))

// ---------------- scratch (device globals) ----------------
__device__ bf16  g_xT_h [(size_t)BB * HW * CIN];
__device__ bf16  g_xT_l [(size_t)BB * HW * CIN];
__device__ bf16  g_b1_h [(size_t)BB * HW * COUT];
__device__ bf16  g_b1_l [(size_t)BB * HW * COUT];
__device__ bf16  g_b2_h [(size_t)BB * HW * CIN];
__device__ bf16  g_b2_l [(size_t)BB * HW * CIN];
__device__ float g_buf1 [(size_t)BB * HW * COUT];
__device__ float g_att  [(size_t)BB * HW * MCB];
__device__ bf16  g_att_h[(size_t)BB * HW * MCB];
__device__ bf16  g_att_l[(size_t)BB * HW * MCB];
__device__ bf16  g_ct_h [MCB * COUT];
__device__ bf16  g_ct_l [MCB * COUT];
__device__ bf16  g_c_h  [COUT * MCB];
__device__ bf16  g_c_l  [COUT * MCB];
__device__ bf16  g_w1_h [COUT * CIN];
__device__ bf16  g_w1_l [COUT * CIN];
__device__ bf16  g_w2_h [CIN * COUT];
__device__ bf16  g_w2_l [CIN * COUT];
__device__ bf16  g_w3_h [CIN * CIN];
__device__ bf16  g_w3_l [CIN * CIN];
__device__ float g_colsum[BB * MCB];
__device__ float g_sum [CIN];
__device__ float g_sum2[CIN];
__device__ float g_scale[CIN];
__device__ float g_shift[CIN];

// ---------------- helpers ----------------
__device__ __forceinline__ uint32_t smem_u32(const void* p) {
    uint32_t a;
    asm("{ .reg .u64 t; cvta.to.shared.u64 t, %1; cvt.u32.u64 %0, t; }" : "=r"(a) : "l"(p));
    return a;
}
__device__ __forceinline__ void cp16(uint32_t dst, const void* src) {
    asm volatile("cp.async.cg.shared.global [%0], [%1], 16;" :: "r"(dst), "l"(src));
}
__device__ __forceinline__ void cp_commit() {
    asm volatile("cp.async.commit_group;" ::: "memory");
}
__device__ __forceinline__ void cp_wait1() {
    asm volatile("cp.async.wait_group 1;" ::: "memory");
}
__device__ __forceinline__ void ldmatrix_x4(uint32_t& r0, uint32_t& r1, uint32_t& r2, uint32_t& r3, uint32_t addr) {
    asm volatile("ldmatrix.sync.aligned.m8n8.x4.shared.b16 {%0,%1,%2,%3}, [%4];"
                 : "=r"(r0), "=r"(r1), "=r"(r2), "=r"(r3) : "r"(addr));
}
__device__ __forceinline__ void ldmatrix_x2(uint32_t& r0, uint32_t& r1, uint32_t addr) {
    asm volatile("ldmatrix.sync.aligned.m8n8.x2.shared.b16 {%0,%1}, [%2];"
                 : "=r"(r0), "=r"(r1) : "r"(addr));
}
__device__ __forceinline__ void mma_bf16(float* c, uint32_t a0, uint32_t a1, uint32_t a2, uint32_t a3,
                                         uint32_t b0, uint32_t b1) {
    asm volatile("mma.sync.aligned.m16n8k16.row.col.f32.bf16.bf16.f32 "
                 "{%0,%1,%2,%3}, {%4,%5,%6,%7}, {%8,%9}, {%0,%1,%2,%3};"
                 : "+f"(c[0]), "+f"(c[1]), "+f"(c[2]), "+f"(c[3])
                 : "r"(a0), "r"(a1), "r"(a2), "r"(a3), "r"(b0), "r"(b1));
}
__device__ __forceinline__ uint32_t pack_bf2(float x, float y) {
    __nv_bfloat162 h = __floats2bfloat162_rn(x, y);
    return *(uint32_t*)&h;
}
__device__ __forceinline__ void split1(float v, bf16& h, bf16& l) {
    h = __float2bfloat16_rn(v);
    l = __float2bfloat16_rn(v - __bfloat162float(h));
}

// ---------------- split bf16x3 GEMM, 3-stage cp.async, SW64 ----------------
// C[m,n] = sum_k A[m,k]*B[n,k] (+bias[n]).
// A = (Ah, Al) planes [Mtot,Kd] K-contig, batch stride aS; B planes shared.
// Output: fp32 Cf or split (Chp, Clp). CTA tile 128 x NT x 32; 8 warps (2x4).
template<int NT, bool BIAS, bool SPLIT_OUT>
__global__ __launch_bounds__(256, 2)
void gemm_sp(const bf16* __restrict__ Ahg, const bf16* __restrict__ Alg,
             const bf16* __restrict__ Bhg, const bf16* __restrict__ Blg,
             const float* __restrict__ bias,
             float* __restrict__ Cf, bf16* __restrict__ Chp, bf16* __restrict__ Clp,
             int Kd, int Ntot, size_t aS, size_t cS)
{
    constexpr int WN = NT / 4;
    constexpr int NF = WN / 8;
    constexpr int OFF_AL = 128 * 64;              // 8192
    constexpr int OFF_BH = 2 * 128 * 64;          // 16384
    constexpr int OFF_BL = OFF_BH + NT * 64;
    constexpr int STAGE  = OFF_BH + 2 * NT * 64;  // 32768 (NT=128) / 28672 (NT=96)

    extern __shared__ char dsm[];
    const uint32_t sbase = smem_u32(dsm);

    const int tid = threadIdx.x;
    const int lane = tid & 31;
    const int wid = tid >> 5;
    const int wm = wid & 1;
    const int wn = wid >> 1;
    const int m0 = blockIdx.y * 128;
    const int n0 = blockIdx.x * NT;
    const int z  = blockIdx.z;

    const bf16* Ah = Ahg + (size_t)z * aS + (size_t)m0 * Kd;
    const bf16* Al = Alg + (size_t)z * aS + (size_t)m0 * Kd;
    const bf16* Bh = Bhg + (size_t)n0 * Kd;
    const bf16* Bl = Blg + (size_t)n0 * Kd;

    const int NC = Kd / BK;

    float acc[4][NF][4];
#pragma unroll
    for (int mi = 0; mi < 4; ++mi)
#pragma unroll
        for (int ni = 0; ni < NF; ++ni)
#pragma unroll
            for (int j = 0; j < 4; ++j) acc[mi][ni][j] = 0.f;

    auto load_stage = [&](int i) {
        if (i < NC) {
            const uint32_t st = sbase + (i % 3) * STAGE;
            const int k0 = i * BK;
            // A: 128 rows x 4 chunks x 2 planes
#pragma unroll
            for (int it = 0; it < 2; ++it) {
                int q = tid + it * 256;
                int row = q >> 2, ch = q & 3;
                uint32_t so = SWZ((uint32_t)(row * 64 + ch * 16));
                size_t go = (size_t)row * Kd + k0 + ch * 8;
                cp16(st + so, Ah + go);
                cp16(st + OFF_AL + so, Al + go);
            }
            // B: NT rows x 4 chunks x 2 planes
#pragma unroll
            for (int it = 0; it < (NT * 4 + 255) / 256; ++it) {
                int q = tid + it * 256;
                if (NT * 4 % 256 == 0 || q < NT * 4) {
                    int row = q >> 2, ch = q & 3;
                    uint32_t so = SWZ((uint32_t)(row * 64 + ch * 16));
                    size_t go = (size_t)row * Kd + k0 + ch * 8;
                    cp16(st + OFF_BH + so, Bh + go);
                    cp16(st + OFF_BL + so, Bl + go);
                }
            }
        }
        cp_commit();
    };

    load_stage(0);
    load_stage(1);

    const int arow = wm * 64;
    const int brow = wn * WN;
    const int l7 = lane & 7;
    const int aq = lane >> 3;                 // 0..3
    const int arsel = (aq & 1) * 8;           // row +8 select
    const int acsel = (aq >> 1) * 16;         // k8-15 chunk select
    const int b4r = ((lane >> 4) & 1) * 8;    // x4 B: upper pair rows
    const int b4c = ((lane >> 3) & 1) * 16;   // x4 B: k chunk
    const int b2c = ((lane >> 3) & 1) * 16;   // x2 B chunk (lanes 0-15)

    for (int i = 0; i < NC; ++i) {
        cp_wait1();
        __syncthreads();
        load_stage(i + 2);   // into slot (i+2)%3 = (i-1)%3, safe after sync

        const uint32_t st = sbase + (i % 3) * STAGE;
        const uint32_t sAh = st;
        const uint32_t sAl = st + OFF_AL;
        const uint32_t sBh = st + OFF_BH;
        const uint32_t sBl = st + OFF_BL;

#pragma unroll
        for (int k16 = 0; k16 < 2; ++k16) {
            const int kb = k16 * 32;
            uint32_t bh[NF][2], bl[NF][2];
            // B fragments: x4 loads two n8 frags at once
#pragma unroll
            for (int p = 0; p < NF / 2; ++p) {
                uint32_t bo = SWZ((uint32_t)((brow + p * 16 + b4r + l7) * 64 + kb + b4c));
                ldmatrix_x4(bh[2*p][0], bh[2*p][1], bh[2*p+1][0], bh[2*p+1][1], sBh + bo);
                ldmatrix_x4(bl[2*p][0], bl[2*p][1], bl[2*p+1][0], bl[2*p+1][1], sBl + bo);
            }
            if (NF & 1) {
                const int ni = NF - 1;
                uint32_t bo = SWZ((uint32_t)((brow + ni * 8 + l7) * 64 + kb + b2c));
                ldmatrix_x2(bh[ni][0], bh[ni][1], sBh + bo);
                ldmatrix_x2(bl[ni][0], bl[ni][1], sBl + bo);
            }
#pragma unroll
            for (int mi = 0; mi < 4; ++mi) {
                uint32_t ao = SWZ((uint32_t)((arow + mi * 16 + arsel + l7) * 64 + kb + acsel));
                uint32_t ah0, ah1, ah2, ah3, al0, al1, al2, al3;
                ldmatrix_x4(ah0, ah1, ah2, ah3, sAh + ao);
                ldmatrix_x4(al0, al1, al2, al3, sAl + ao);
#pragma unroll
                for (int ni = 0; ni < NF; ++ni) {
                    mma_bf16(acc[mi][ni], ah0, ah1, ah2, ah3, bh[ni][0], bh[ni][1]);
                    mma_bf16(acc[mi][ni], ah0, ah1, ah2, ah3, bl[ni][0], bl[ni][1]);
                    mma_bf16(acc[mi][ni], al0, al1, al2, al3, bh[ni][0], bh[ni][1]);
                }
            }
        }
    }

    // ---- epilogue ----
    const int l4 = lane >> 2;
    const int lc = (lane & 3) * 2;
#pragma unroll
    for (int mi = 0; mi < 4; ++mi) {
        const int row = m0 + wm * 64 + mi * 16 + l4;
#pragma unroll
        for (int ni = 0; ni < NF; ++ni) {
            const int col = n0 + wn * WN + ni * 8 + lc;
            float b0 = BIAS ? bias[col] : 0.f;
            float b1 = BIAS ? bias[col + 1] : 0.f;
            float v00 = acc[mi][ni][0] + b0, v01 = acc[mi][ni][1] + b1;
            float v10 = acc[mi][ni][2] + b0, v11 = acc[mi][ni][3] + b1;
            if (SPLIT_OUT) {
                bf16 h0, l0, h1, l1;
                size_t o0 = (size_t)z * cS + (size_t)row * Ntot + col;
                size_t o1 = (size_t)z * cS + (size_t)(row + 8) * Ntot + col;
                split1(v00, h0, l0); split1(v01, h1, l1);
                *(uint32_t*)(Chp + o0) = pack_bf2(__bfloat162float(h0), __bfloat162float(h1));
                *(uint32_t*)(Clp + o0) = pack_bf2(__bfloat162float(l0), __bfloat162float(l1));
                split1(v10, h0, l0); split1(v11, h1, l1);
                *(uint32_t*)(Chp + o1) = pack_bf2(__bfloat162float(h0), __bfloat162float(h1));
                *(uint32_t*)(Clp + o1) = pack_bf2(__bfloat162float(l0), __bfloat162float(l1));
            } else {
                float* C = Cf + (size_t)z * cS;
                float2 w0 = { v00, v01 };
                float2 w1 = { v10, v11 };
                *(float2*)(C + (size_t)row * Ntot + col) = w0;
                *(float2*)(C + (size_t)(row + 8) * Ntot + col) = w1;
            }
        }
    }
}

// ---------------- prep kernels ----------------
__global__ void split_kernel(const float* __restrict__ in, bf16* __restrict__ h, bf16* __restrict__ l, int n)
{
    int i = blockIdx.x * 256 + threadIdx.x;
    if (i < n) {
        float v = in[i];
        bf16 hh, ll;
        split1(v, hh, ll);
        h[i] = hh; l[i] = ll;
    }
}

__global__ void transpose_in_split(const float* __restrict__ in, bf16* __restrict__ oh, bf16* __restrict__ ol)
{
    __shared__ float t[32][33];
    const int b = blockIdx.z;
    const int n0 = blockIdx.x * 32, c0 = blockIdx.y * 32;
    const float* ip = in + (size_t)b * CIN * HW;
#pragma unroll
    for (int i = 0; i < 32; i += 8)
        t[threadIdx.y + i][threadIdx.x] = ip[(size_t)(c0 + threadIdx.y + i) * HW + n0 + threadIdx.x];
    __syncthreads();
#pragma unroll
    for (int i = 0; i < 32; i += 8) {
        float v = t[threadIdx.x][threadIdx.y + i];
        bf16 hh, ll;
        split1(v, hh, ll);
        size_t o = (size_t)b * HW * CIN + (size_t)(n0 + threadIdx.y + i) * CIN + c0 + threadIdx.x;
        oh[o] = hh; ol[o] = ll;
    }
}

__global__ void transpose_centers_split(const float* __restrict__ in, bf16* __restrict__ oh, bf16* __restrict__ ol)
{
    int idx = blockIdx.x * 256 + threadIdx.x;
    if (idx < COUT * MCB) {
        int c = idx / MCB, k = idx % MCB;
        bf16 hh, ll;
        split1(in[idx], hh, ll);
        oh[k * COUT + c] = hh;
        ol[k * COUT + c] = ll;
    }
}

// ---------------- softmax + double-norm ----------------
__global__ void softmax_colsum_kernel(float* __restrict__ att, float* __restrict__ colsum)
{
    const int warp = threadIdx.x >> 5;
    const int lane = threadIdx.x & 31;
    const int b = blockIdx.y;
    const int rowBase = blockIdx.x * 256 + warp * 32;
    float cacc[6] = {0.f, 0.f, 0.f, 0.f, 0.f, 0.f};

    for (int r = 0; r < 32; ++r) {
        const int n = rowBase + r;
        float* p = att + ((size_t)b * HW + n) * MCB;
        float v[6];
        float mx = -1e30f;
#pragma unroll
        for (int j = 0; j < 6; ++j) { v[j] = p[j * 32 + lane]; mx = fmaxf(mx, v[j]); }
#pragma unroll
        for (int o = 16; o > 0; o >>= 1) mx = fmaxf(mx, __shfl_xor_sync(0xffffffffu, mx, o));
        float s = 0.f;
#pragma unroll
        for (int j = 0; j < 6; ++j) { v[j] = expf(v[j] - mx); s += v[j]; }
#pragma unroll
        for (int o = 16; o > 0; o >>= 1) s += __shfl_xor_sync(0xffffffffu, s, o);
        const float inv = 1.f / s;
#pragma unroll
        for (int j = 0; j < 6; ++j) {
            float ov = v[j] * inv;
            p[j * 32 + lane] = ov;
            cacc[j] += ov;
        }
    }
#pragma unroll
    for (int j = 0; j < 6; ++j)
        atomicAdd(&colsum[b * MCB + j * 32 + lane], cacc[j]);
}

__global__ void zero_colsum_kernel(float* cs)
{
    int i = blockIdx.x * 1024 + threadIdx.x;
    if (i < BB * MCB) cs[i] = 0.f;
}
__global__ void rcp_colsum_kernel(float* cs)
{
    int i = blockIdx.x * 1024 + threadIdx.x;
    if (i < BB * MCB) cs[i] = 1.f / (1e-6f + cs[i]);
}
__global__ void scale_att_split(const float* __restrict__ att, const float* __restrict__ rcp,
                                bf16* __restrict__ oh, bf16* __restrict__ ol)
{
    size_t i = (size_t)blockIdx.x * blockDim.x + threadIdx.x;   // float4 index
    const int k4 = (int)(i % 48);
    const size_t row = i / 48;
    const int b = (int)(row >> 12);
    float4 v = ((const float4*)att)[i];
    const float4 r = ((const float4*)rcp)[b * 48 + k4];
    v.x *= r.x; v.y *= r.y; v.z *= r.z; v.w *= r.w;
    bf16 hx, lx, hy, ly, hz, lz, hw, lw;
    split1(v.x, hx, lx); split1(v.y, hy, ly); split1(v.z, hz, lz); split1(v.w, hw, lw);
    uint2 ho = { pack_bf2(__bfloat162float(hx), __bfloat162float(hy)),
                 pack_bf2(__bfloat162float(hz), __bfloat162float(hw)) };
    uint2 lo = { pack_bf2(__bfloat162float(lx), __bfloat162float(ly)),
                 pack_bf2(__bfloat162float(lz), __bfloat162float(lw)) };
    *(uint2*)(oh + i * 4) = ho;
    *(uint2*)(ol + i * 4) = lo;
}

// ---------------- BN ----------------
__global__ void zero_stats_kernel(float* sum, float* sum2)
{
    int i = blockIdx.x * 512 + threadIdx.x;
    if (i < CIN) { sum[i] = 0.f; sum2[i] = 0.f; }
}
__global__ void bn_stats_cols_kernel(const float* __restrict__ t, float* __restrict__ sum, float* __restrict__ sum2)
{
    const int c = threadIdx.x;
    const size_t r0 = (size_t)blockIdx.x * 256;
    const float* p = t + r0 * CIN + c;
    float s = 0.f, s2 = 0.f;
    for (int r = 0; r < 256; ++r) {
        float v = p[(size_t)r * CIN];
        s += v; s2 += v * v;
    }
    atomicAdd(&sum[c], s);
    atomicAdd(&sum2[c], s2);
}
__global__ void bn_finalize_kernel(const float* __restrict__ sum, const float* __restrict__ sum2,
                                   const float* __restrict__ gamma, const float* __restrict__ beta,
                                   float* __restrict__ scale, float* __restrict__ shift)
{
    int c = threadIdx.x;
    const float N = (float)((size_t)BB * HW);
    float mean = sum[c] / N;
    float var = sum2[c] / N - mean * mean;
    float sc = gamma[c] * rsqrtf(var + EPS_BN);
    scale[c] = sc;
    shift[c] = beta[c] - mean * sc;
}
__global__ void bn_apply_res_split(const float* __restrict__ t,
                                   const bf16* __restrict__ xh, const bf16* __restrict__ xl,
                                   const float* __restrict__ scale, const float* __restrict__ shift,
                                   bf16* __restrict__ oh, bf16* __restrict__ ol)
{
    size_t i = (size_t)blockIdx.x * blockDim.x + threadIdx.x;   // float4 index
    const int c4 = (int)(i & 127);
    const float4 sc = ((const float4*)scale)[c4];
    const float4 sh = ((const float4*)shift)[c4];
    float4 v = ((const float4*)t)[i];
    uint2 xhu = *(const uint2*)(xh + i * 4);
    uint2 xlu = *(const uint2*)(xl + i * 4);
    __nv_bfloat162 xh0 = *(__nv_bfloat162*)&xhu.x;
    __nv_bfloat162 xh1 = *(__nv_bfloat162*)&xhu.y;
    __nv_bfloat162 xl0 = *(__nv_bfloat162*)&xlu.x;
    __nv_bfloat162 xl1 = *(__nv_bfloat162*)&xlu.y;
    v.x = fmaxf(fmaf(sc.x, v.x, sh.x), 0.f) + __bfloat162float(xh0.x) + __bfloat162float(xl0.x);
    v.y = fmaxf(fmaf(sc.y, v.y, sh.y), 0.f) + __bfloat162float(xh0.y) + __bfloat162float(xl0.y);
    v.z = fmaxf(fmaf(sc.z, v.z, sh.z), 0.f) + __bfloat162float(xh1.x) + __bfloat162float(xl1.x);
    v.w = fmaxf(fmaf(sc.w, v.w, sh.w), 0.f) + __bfloat162float(xh1.y) + __bfloat162float(xl1.y);
    bf16 hx, lx, hy, ly, hz, lz, hw, lw;
    split1(v.x, hx, lx); split1(v.y, hy, ly); split1(v.z, hz, lz); split1(v.w, hw, lw);
    uint2 ho = { pack_bf2(__bfloat162float(hx), __bfloat162float(hy)),
                 pack_bf2(__bfloat162float(hz), __bfloat162float(hw)) };
    uint2 lo = { pack_bf2(__bfloat162float(lx), __bfloat162float(ly)),
                 pack_bf2(__bfloat162float(lz), __bfloat162float(lw)) };
    *(uint2*)(oh + i * 4) = ho;
    *(uint2*)(ol + i * 4) = lo;
}

__global__ void bn_apply_transpose_kernel(const float* __restrict__ in,
                                          const float* __restrict__ scale, const float* __restrict__ shift,
                                          float* __restrict__ out)
{
    __shared__ float t[32][33];
    const int b = blockIdx.z;
    const int n0 = blockIdx.x * 32, c0 = blockIdx.y * 32;
    const float* ip = in + (size_t)b * HW * CIN;
    float* op = out + (size_t)b * CIN * HW;
    const int c = c0 + threadIdx.x;
    const float sc = scale[c], sh = shift[c];
#pragma unroll
    for (int i = 0; i < 32; i += 8) {
        float v = ip[(size_t)(n0 + threadIdx.y + i) * CIN + c];
        t[threadIdx.y + i][threadIdx.x] = fmaxf(fmaf(sc, v, sh), 0.f);
    }
    __syncthreads();
#pragma unroll
    for (int i = 0; i < 32; i += 8)
        op[(size_t)(c0 + threadIdx.y + i) * HW + n0 + threadIdx.x] = t[threadIdx.x][threadIdx.y + i];
}

// ---------------- launch ----------------
extern "C" void kernel_launch(void* const* d_in, const int* in_sizes, int n_in,
                              void* d_out, int out_size)
{
    const float* x       = (const float*)d_in[0];
    const float* centers = (const float*)d_in[1];
    const float* conv1_w = (const float*)d_in[2];
    const float* conv1_b = (const float*)d_in[3];
    const float* conv2_w = (const float*)d_in[4];
    const float* bn2_g   = (const float*)d_in[5];
    const float* bn2_b   = (const float*)d_in[6];
    const float* conv3_w = (const float*)d_in[7];
    const float* conv3_b = (const float*)d_in[8];
    const float* bn3_g   = (const float*)d_in[9];
    const float* bn3_b   = (const float*)d_in[10];
    float* out = (float*)d_out;

    bf16 *xTh, *xTl, *b1h, *b1l, *b2h, *b2l, *atth, *attl, *cth, *ctl, *ch, *cl;
    bf16 *w1h, *w1l, *w2h, *w2l, *w3h, *w3l;
    float *buf1, *att, *colsum, *sum, *sum2, *scale, *shift;
    cudaGetSymbolAddress((void**)&xTh, g_xT_h);  cudaGetSymbolAddress((void**)&xTl, g_xT_l);
    cudaGetSymbolAddress((void**)&b1h, g_b1_h);  cudaGetSymbolAddress((void**)&b1l, g_b1_l);
    cudaGetSymbolAddress((void**)&b2h, g_b2_h);  cudaGetSymbolAddress((void**)&b2l, g_b2_l);
    cudaGetSymbolAddress((void**)&atth, g_att_h); cudaGetSymbolAddress((void**)&attl, g_att_l);
    cudaGetSymbolAddress((void**)&cth, g_ct_h);  cudaGetSymbolAddress((void**)&ctl, g_ct_l);
    cudaGetSymbolAddress((void**)&ch, g_c_h);    cudaGetSymbolAddress((void**)&cl, g_c_l);
    cudaGetSymbolAddress((void**)&w1h, g_w1_h);  cudaGetSymbolAddress((void**)&w1l, g_w1_l);
    cudaGetSymbolAddress((void**)&w2h, g_w2_h);  cudaGetSymbolAddress((void**)&w2l, g_w2_l);
    cudaGetSymbolAddress((void**)&w3h, g_w3_h);  cudaGetSymbolAddress((void**)&w3l, g_w3_l);
    cudaGetSymbolAddress((void**)&buf1, g_buf1);
    cudaGetSymbolAddress((void**)&att, g_att);
    cudaGetSymbolAddress((void**)&colsum, g_colsum);
    cudaGetSymbolAddress((void**)&sum, g_sum);
    cudaGetSymbolAddress((void**)&sum2, g_sum2);
    cudaGetSymbolAddress((void**)&scale, g_scale);
    cudaGetSymbolAddress((void**)&shift, g_shift);

    const size_t S  = (size_t)HW * CIN;
    const size_t SA = (size_t)HW * MCB;

    const int SM128 = 3 * 32768;   // 98304
    const int SM96  = 3 * 28672;   // 86016
    cudaFuncSetAttribute(gemm_sp<128, true,  true >, cudaFuncAttributeMaxDynamicSharedMemorySize, SM128);
    cudaFuncSetAttribute(gemm_sp<96,  false, false>, cudaFuncAttributeMaxDynamicSharedMemorySize, SM96);
    cudaFuncSetAttribute(gemm_sp<128, false, true >, cudaFuncAttributeMaxDynamicSharedMemorySize, SM128);
    cudaFuncSetAttribute(gemm_sp<128, false, false>, cudaFuncAttributeMaxDynamicSharedMemorySize, SM128);
    cudaFuncSetAttribute(gemm_sp<128, true,  false>, cudaFuncAttributeMaxDynamicSharedMemorySize, SM128);

    // 0. prep: transpose + split everything
    transpose_in_split<<<dim3(HW / 32, CIN / 32, BB), dim3(32, 8)>>>(x, xTh, xTl);
    transpose_centers_split<<<(COUT * MCB + 255) / 256, 256>>>(centers, cth, ctl);
    split_kernel<<<(COUT * MCB + 255) / 256, 256>>>(centers, ch, cl, COUT * MCB);
    split_kernel<<<(COUT * CIN + 255) / 256, 256>>>(conv1_w, w1h, w1l, COUT * CIN);
    split_kernel<<<(CIN * COUT + 255) / 256, 256>>>(conv2_w, w2h, w2l, CIN * COUT);
    split_kernel<<<(CIN * CIN + 255) / 256, 256>>>(conv3_w, w3h, w3l, CIN * CIN);

    // 1. conv1 -> split buf1 planes
    gemm_sp<128, true, true><<<dim3(4, 32, BB), 256, SM128>>>(
        xTh, xTl, w1h, w1l, conv1_b, nullptr, b1h, b1l, CIN, COUT, S, S);

    // 2. att = buf1 @ ct^T -> fp32 att
    gemm_sp<96, false, false><<<dim3(2, 32, BB), 256, SM96>>>(
        b1h, b1l, cth, ctl, nullptr, att, nullptr, nullptr, COUT, MCB, S, SA);

    // 3. softmax + double normalization (+ split att)
    zero_colsum_kernel<<<3, 1024>>>(colsum);
    softmax_colsum_kernel<<<dim3(HW / 256, BB), 256>>>(att, colsum);
    rcp_colsum_kernel<<<3, 1024>>>(colsum);
    scale_att_split<<<(unsigned)(((size_t)BB * HW * 48) / 256), 256>>>(att, colsum, atth, attl);

    // 4. recon = att @ centers^T -> split buf2 planes
    gemm_sp<128, false, true><<<dim3(4, 32, BB), 256, SM128>>>(
        atth, attl, ch, cl, nullptr, nullptr, b2h, b2l, MCB, COUT, SA, S);

    // 5. conv2 -> fp32 buf1
    gemm_sp<128, false, false><<<dim3(4, 32, BB), 256, SM128>>>(
        b2h, b2l, w2h, w2l, nullptr, buf1, nullptr, nullptr, COUT, CIN, S, S);

    // 6. BN2 + ReLU + residual -> split buf2 planes
    zero_stats_kernel<<<1, 512>>>(sum, sum2);
    bn_stats_cols_kernel<<<256, 512>>>(buf1, sum, sum2);
    bn_finalize_kernel<<<1, 512>>>(sum, sum2, bn2_g, bn2_b, scale, shift);
    bn_apply_res_split<<<(unsigned)(((size_t)BB * S / 4) / 256), 256>>>(buf1, xTh, xTl, scale, shift, b2h, b2l);

    // 7. conv3 -> fp32 buf1
    gemm_sp<128, true, false><<<dim3(4, 32, BB), 256, SM128>>>(
        b2h, b2l, w3h, w3l, conv3_b, buf1, nullptr, nullptr, CIN, CIN, S, S);

    // 8. BN3 + ReLU + transpose -> out
    zero_stats_kernel<<<1, 512>>>(sum, sum2);
    bn_stats_cols_kernel<<<256, 512>>>(buf1, sum, sum2);
    bn_finalize_kernel<<<1, 512>>>(sum, sum2, bn3_g, bn3_b, scale, shift);
    bn_apply_transpose_kernel<<<dim3(HW / 32, CIN / 32, BB), dim3(32, 8)>>>(buf1, scale, shift, out);
}

// round 6
// speedup vs baseline: 2.4267x; 1.0162x over previous
#include <cuda_runtime.h>
#include <cuda_bf16.h>
#include <math.h>
#include <stdint.h>

// ---------------- problem constants ----------------
#define BB   16
#define CIN  512
#define COUT 512
#define HW   4096
#define MCB  192
#define EPS_BN 1e-5f
#define BK   32

typedef __nv_bfloat16 bf16;

#define SWZ(o) ((o) ^ (((o) >> 3) & 0x30))

// ---------------- scratch (device globals) ----------------
__device__ bf16  g_xT_h [(size_t)BB * HW * CIN];
__device__ bf16  g_xT_l [(size_t)BB * HW * CIN];
__device__ bf16  g_b1_h [(size_t)BB * HW * COUT];
__device__ bf16  g_b1_l [(size_t)BB * HW * COUT];
__device__ bf16  g_b2_h [(size_t)BB * HW * CIN];
__device__ bf16  g_b2_l [(size_t)BB * HW * CIN];
__device__ float g_buf1 [(size_t)BB * HW * COUT];
__device__ float g_att  [(size_t)BB * HW * MCB];
__device__ bf16  g_att_h[(size_t)BB * HW * MCB];
__device__ bf16  g_att_l[(size_t)BB * HW * MCB];
__device__ bf16  g_ct_h [MCB * COUT];
__device__ bf16  g_ct_l [MCB * COUT];
__device__ bf16  g_c_h  [COUT * MCB];
__device__ bf16  g_c_l  [COUT * MCB];
__device__ bf16  g_w1_h [COUT * CIN];
__device__ bf16  g_w1_l [COUT * CIN];
__device__ bf16  g_w2_h [CIN * COUT];
__device__ bf16  g_w2_l [CIN * COUT];
__device__ bf16  g_w3_h [CIN * CIN];
__device__ bf16  g_w3_l [CIN * CIN];
__device__ float g_colsum[BB * MCB];
__device__ float g_sum [CIN];
__device__ float g_sum2[CIN];
__device__ float g_scale[CIN];
__device__ float g_shift[CIN];

// ---------------- helpers ----------------
__device__ __forceinline__ uint32_t smem_u32(const void* p) {
    uint32_t a;
    asm("{ .reg .u64 t; cvta.to.shared.u64 t, %1; cvt.u32.u64 %0, t; }" : "=r"(a) : "l"(p));
    return a;
}
__device__ __forceinline__ void cp16(uint32_t dst, const void* src) {
    asm volatile("cp.async.cg.shared.global [%0], [%1], 16;" :: "r"(dst), "l"(src));
}
__device__ __forceinline__ void cp_commit() {
    asm volatile("cp.async.commit_group;" ::: "memory");
}
__device__ __forceinline__ void cp_wait1() {
    asm volatile("cp.async.wait_group 1;" ::: "memory");
}
__device__ __forceinline__ void ldmatrix_x4(uint32_t& r0, uint32_t& r1, uint32_t& r2, uint32_t& r3, uint32_t addr) {
    asm volatile("ldmatrix.sync.aligned.m8n8.x4.shared.b16 {%0,%1,%2,%3}, [%4];"
                 : "=r"(r0), "=r"(r1), "=r"(r2), "=r"(r3) : "r"(addr));
}
__device__ __forceinline__ void ldmatrix_x2(uint32_t& r0, uint32_t& r1, uint32_t addr) {
    asm volatile("ldmatrix.sync.aligned.m8n8.x2.shared.b16 {%0,%1}, [%2];"
                 : "=r"(r0), "=r"(r1) : "r"(addr));
}
__device__ __forceinline__ void mma_bf16(float* c, uint32_t a0, uint32_t a1, uint32_t a2, uint32_t a3,
                                         uint32_t b0, uint32_t b1) {
    asm volatile("mma.sync.aligned.m16n8k16.row.col.f32.bf16.bf16.f32 "
                 "{%0,%1,%2,%3}, {%4,%5,%6,%7}, {%8,%9}, {%0,%1,%2,%3};"
                 : "+f"(c[0]), "+f"(c[1]), "+f"(c[2]), "+f"(c[3])
                 : "r"(a0), "r"(a1), "r"(a2), "r"(a3), "r"(b0), "r"(b1));
}
__device__ __forceinline__ uint32_t pack_bf2(float x, float y) {
    __nv_bfloat162 h = __floats2bfloat162_rn(x, y);
    return *(uint32_t*)&h;
}
__device__ __forceinline__ void split1(float v, bf16& h, bf16& l) {
    h = __float2bfloat16_rn(v);
    l = __float2bfloat16_rn(v - __bfloat162float(h));
}

// ---------------- split bf16x3 GEMM, 3-stage cp.async, SW64 ----------------
// C[m,n] = sum_k A[m,k]*B[n,k] (+bias[n]). Optional fused BN column stats.
template<int NT, bool BIAS, bool SPLIT_OUT, bool BNSTAT>
__global__ __launch_bounds__(256, 2)
void gemm_sp(const bf16* __restrict__ Ahg, const bf16* __restrict__ Alg,
             const bf16* __restrict__ Bhg, const bf16* __restrict__ Blg,
             const float* __restrict__ bias,
             float* __restrict__ Cf, bf16* __restrict__ Chp, bf16* __restrict__ Clp,
             float* __restrict__ gsum, float* __restrict__ gsum2,
             int Kd, int Ntot, size_t aS, size_t cS)
{
    constexpr int WN = NT / 4;
    constexpr int NF = WN / 8;
    constexpr int OFF_AL = 128 * 64;
    constexpr int OFF_BH = 2 * 128 * 64;
    constexpr int OFF_BL = OFF_BH + NT * 64;
    constexpr int STAGE  = OFF_BH + 2 * NT * 64;

    extern __shared__ char dsm[];
    const uint32_t sbase = smem_u32(dsm);
    __shared__ float bn_s[NT];
    __shared__ float bn_s2[NT];

    const int tid = threadIdx.x;
    const int lane = tid & 31;
    const int wid = tid >> 5;
    const int wm = wid & 1;
    const int wn = wid >> 1;
    const int m0 = blockIdx.y * 128;
    const int n0 = blockIdx.x * NT;
    const int z  = blockIdx.z;

    const bf16* Ah = Ahg + (size_t)z * aS + (size_t)m0 * Kd;
    const bf16* Al = Alg + (size_t)z * aS + (size_t)m0 * Kd;
    const bf16* Bh = Bhg + (size_t)n0 * Kd;
    const bf16* Bl = Blg + (size_t)n0 * Kd;

    const int NC = Kd / BK;

    float acc[4][NF][4];
#pragma unroll
    for (int mi = 0; mi < 4; ++mi)
#pragma unroll
        for (int ni = 0; ni < NF; ++ni)
#pragma unroll
            for (int j = 0; j < 4; ++j) acc[mi][ni][j] = 0.f;

    auto load_stage = [&](int i) {
        if (i < NC) {
            const uint32_t st = sbase + (i % 3) * STAGE;
            const int k0 = i * BK;
#pragma unroll
            for (int it = 0; it < 2; ++it) {
                int q = tid + it * 256;
                int row = q >> 2, ch = q & 3;
                uint32_t so = SWZ((uint32_t)(row * 64 + ch * 16));
                size_t go = (size_t)row * Kd + k0 + ch * 8;
                cp16(st + so, Ah + go);
                cp16(st + OFF_AL + so, Al + go);
            }
#pragma unroll
            for (int it = 0; it < (NT * 4 + 255) / 256; ++it) {
                int q = tid + it * 256;
                if (NT * 4 % 256 == 0 || q < NT * 4) {
                    int row = q >> 2, ch = q & 3;
                    uint32_t so = SWZ((uint32_t)(row * 64 + ch * 16));
                    size_t go = (size_t)row * Kd + k0 + ch * 8;
                    cp16(st + OFF_BH + so, Bh + go);
                    cp16(st + OFF_BL + so, Bl + go);
                }
            }
        }
        cp_commit();
    };

    load_stage(0);
    load_stage(1);

    const int arow = wm * 64;
    const int brow = wn * WN;
    const int l7 = lane & 7;
    const int aq = lane >> 3;
    const int arsel = (aq & 1) * 8;
    const int acsel = (aq >> 1) * 16;
    const int b4r = ((lane >> 4) & 1) * 8;
    const int b4c = ((lane >> 3) & 1) * 16;
    const int b2c = ((lane >> 3) & 1) * 16;

    for (int i = 0; i < NC; ++i) {
        cp_wait1();
        __syncthreads();
        load_stage(i + 2);

        const uint32_t st = sbase + (i % 3) * STAGE;
        const uint32_t sAh = st;
        const uint32_t sAl = st + OFF_AL;
        const uint32_t sBh = st + OFF_BH;
        const uint32_t sBl = st + OFF_BL;

#pragma unroll
        for (int k16 = 0; k16 < 2; ++k16) {
            const int kb = k16 * 32;
            uint32_t bh[NF][2], bl[NF][2];
#pragma unroll
            for (int p = 0; p < NF / 2; ++p) {
                uint32_t bo = SWZ((uint32_t)((brow + p * 16 + b4r + l7) * 64 + kb + b4c));
                ldmatrix_x4(bh[2*p][0], bh[2*p][1], bh[2*p+1][0], bh[2*p+1][1], sBh + bo);
                ldmatrix_x4(bl[2*p][0], bl[2*p][1], bl[2*p+1][0], bl[2*p+1][1], sBl + bo);
            }
            if (NF & 1) {
                const int ni = NF - 1;
                uint32_t bo = SWZ((uint32_t)((brow + ni * 8 + l7) * 64 + kb + b2c));
                ldmatrix_x2(bh[ni][0], bh[ni][1], sBh + bo);
                ldmatrix_x2(bl[ni][0], bl[ni][1], sBl + bo);
            }
#pragma unroll
            for (int mi = 0; mi < 4; ++mi) {
                uint32_t ao = SWZ((uint32_t)((arow + mi * 16 + arsel + l7) * 64 + kb + acsel));
                uint32_t ah0, ah1, ah2, ah3, al0, al1, al2, al3;
                ldmatrix_x4(ah0, ah1, ah2, ah3, sAh + ao);
                ldmatrix_x4(al0, al1, al2, al3, sAl + ao);
                // term-major: same accumulator reused NF apart, not back-to-back
#pragma unroll
                for (int ni = 0; ni < NF; ++ni)
                    mma_bf16(acc[mi][ni], ah0, ah1, ah2, ah3, bh[ni][0], bh[ni][1]);
#pragma unroll
                for (int ni = 0; ni < NF; ++ni)
                    mma_bf16(acc[mi][ni], ah0, ah1, ah2, ah3, bl[ni][0], bl[ni][1]);
#pragma unroll
                for (int ni = 0; ni < NF; ++ni)
                    mma_bf16(acc[mi][ni], al0, al1, al2, al3, bh[ni][0], bh[ni][1]);
            }
        }
    }

    // ---- epilogue ----
    const int l4 = lane >> 2;
    const int lc = (lane & 3) * 2;
    float ps0[NF], ps1[NF], q0s[NF], q1s[NF];
#pragma unroll
    for (int ni = 0; ni < NF; ++ni) { ps0[ni] = ps1[ni] = q0s[ni] = q1s[ni] = 0.f; }

#pragma unroll
    for (int mi = 0; mi < 4; ++mi) {
        const int row = m0 + wm * 64 + mi * 16 + l4;
#pragma unroll
        for (int ni = 0; ni < NF; ++ni) {
            const int col = n0 + wn * WN + ni * 8 + lc;
            float b0 = BIAS ? bias[col] : 0.f;
            float b1 = BIAS ? bias[col + 1] : 0.f;
            float v00 = acc[mi][ni][0] + b0, v01 = acc[mi][ni][1] + b1;
            float v10 = acc[mi][ni][2] + b0, v11 = acc[mi][ni][3] + b1;
            if (BNSTAT) {
                ps0[ni] += v00 + v10;  q0s[ni] += v00 * v00 + v10 * v10;
                ps1[ni] += v01 + v11;  q1s[ni] += v01 * v01 + v11 * v11;
            }
            if (SPLIT_OUT) {
                bf16 h0, l0, h1, l1;
                size_t o0 = (size_t)z * cS + (size_t)row * Ntot + col;
                size_t o1 = (size_t)z * cS + (size_t)(row + 8) * Ntot + col;
                split1(v00, h0, l0); split1(v01, h1, l1);
                *(uint32_t*)(Chp + o0) = pack_bf2(__bfloat162float(h0), __bfloat162float(h1));
                *(uint32_t*)(Clp + o0) = pack_bf2(__bfloat162float(l0), __bfloat162float(l1));
                split1(v10, h0, l0); split1(v11, h1, l1);
                *(uint32_t*)(Chp + o1) = pack_bf2(__bfloat162float(h0), __bfloat162float(h1));
                *(uint32_t*)(Clp + o1) = pack_bf2(__bfloat162float(l0), __bfloat162float(l1));
            } else {
                float* C = Cf + (size_t)z * cS;
                float2 w0 = { v00, v01 };
                float2 w1 = { v10, v11 };
                *(float2*)(C + (size_t)row * Ntot + col) = w0;
                *(float2*)(C + (size_t)(row + 8) * Ntot + col) = w1;
            }
        }
    }

    if (BNSTAT) {
        __syncthreads();
        for (int t = tid; t < NT; t += 256) { bn_s[t] = 0.f; bn_s2[t] = 0.f; }
        __syncthreads();
#pragma unroll
        for (int ni = 0; ni < NF; ++ni) {
            float a = ps0[ni], b = ps1[ni], c = q0s[ni], d = q1s[ni];
#pragma unroll
            for (int o = 4; o <= 16; o <<= 1) {
                a += __shfl_xor_sync(0xffffffffu, a, o);
                b += __shfl_xor_sync(0xffffffffu, b, o);
                c += __shfl_xor_sync(0xffffffffu, c, o);
                d += __shfl_xor_sync(0xffffffffu, d, o);
            }
            if (lane < 4) {
                int cl = wn * WN + ni * 8 + lc;
                atomicAdd(&bn_s[cl], a);  atomicAdd(&bn_s[cl + 1], b);
                atomicAdd(&bn_s2[cl], c); atomicAdd(&bn_s2[cl + 1], d);
            }
        }
        __syncthreads();
        for (int t = tid; t < NT; t += 256) {
            atomicAdd(&gsum[n0 + t], bn_s[t]);
            atomicAdd(&gsum2[n0 + t], bn_s2[t]);
        }
    }
}

// ---------------- prep kernels ----------------
__global__ void split_kernel(const float* __restrict__ in, bf16* __restrict__ h, bf16* __restrict__ l, int n)
{
    int i = blockIdx.x * 256 + threadIdx.x;
    if (i < n) {
        float v = in[i];
        bf16 hh, ll;
        split1(v, hh, ll);
        h[i] = hh; l[i] = ll;
    }
}

__global__ void transpose_in_split(const float* __restrict__ in, bf16* __restrict__ oh, bf16* __restrict__ ol)
{
    __shared__ float t[32][33];
    const int b = blockIdx.z;
    const int n0 = blockIdx.x * 32, c0 = blockIdx.y * 32;
    const float* ip = in + (size_t)b * CIN * HW;
#pragma unroll
    for (int i = 0; i < 32; i += 8)
        t[threadIdx.y + i][threadIdx.x] = ip[(size_t)(c0 + threadIdx.y + i) * HW + n0 + threadIdx.x];
    __syncthreads();
#pragma unroll
    for (int i = 0; i < 32; i += 8) {
        float v = t[threadIdx.x][threadIdx.y + i];
        bf16 hh, ll;
        split1(v, hh, ll);
        size_t o = (size_t)b * HW * CIN + (size_t)(n0 + threadIdx.y + i) * CIN + c0 + threadIdx.x;
        oh[o] = hh; ol[o] = ll;
    }
}

__global__ void transpose_centers_split(const float* __restrict__ in, bf16* __restrict__ oh, bf16* __restrict__ ol)
{
    int idx = blockIdx.x * 256 + threadIdx.x;
    if (idx < COUT * MCB) {
        int c = idx / MCB, k = idx % MCB;
        bf16 hh, ll;
        split1(in[idx], hh, ll);
        oh[k * COUT + c] = hh;
        ol[k * COUT + c] = ll;
    }
}

// ---------------- softmax (two-pass, recompute) ----------------
// pass 1: row softmax -> column sums only (no att writeback)
__global__ void softmax_colsum_pass1(const float* __restrict__ att, float* __restrict__ colsum)
{
    const int warp = threadIdx.x >> 5;
    const int lane = threadIdx.x & 31;
    const int b = blockIdx.y;
    const int rowBase = blockIdx.x * 256 + warp * 32;
    float cacc[6] = {0.f, 0.f, 0.f, 0.f, 0.f, 0.f};

    for (int r = 0; r < 32; ++r) {
        const int n = rowBase + r;
        const float* p = att + ((size_t)b * HW + n) * MCB;
        float v[6];
        float mx = -1e30f;
#pragma unroll
        for (int j = 0; j < 6; ++j) { v[j] = p[j * 32 + lane]; mx = fmaxf(mx, v[j]); }
#pragma unroll
        for (int o = 16; o > 0; o >>= 1) mx = fmaxf(mx, __shfl_xor_sync(0xffffffffu, mx, o));
        float s = 0.f;
#pragma unroll
        for (int j = 0; j < 6; ++j) { v[j] = expf(v[j] - mx); s += v[j]; }
#pragma unroll
        for (int o = 16; o > 0; o >>= 1) s += __shfl_xor_sync(0xffffffffu, s, o);
        const float inv = 1.f / s;
#pragma unroll
        for (int j = 0; j < 6; ++j) cacc[j] += v[j] * inv;
    }
#pragma unroll
    for (int j = 0; j < 6; ++j)
        atomicAdd(&colsum[b * MCB + j * 32 + lane], cacc[j]);
}

__global__ void zero_colsum_kernel(float* cs)
{
    int i = blockIdx.x * 1024 + threadIdx.x;
    if (i < BB * MCB) cs[i] = 0.f;
}

// pass 2: recompute softmax, apply 1/(1e-6+colsum), write split planes
__global__ void softmax_scale_split(const float* __restrict__ att, const float* __restrict__ colsum,
                                    bf16* __restrict__ oh, bf16* __restrict__ ol)
{
    const int warp = threadIdx.x >> 5;
    const int lane = threadIdx.x & 31;
    const int b = blockIdx.y;
    const int rowBase = blockIdx.x * 256 + warp * 32;

    float rinv[6];
#pragma unroll
    for (int j = 0; j < 6; ++j)
        rinv[j] = 1.f / (1e-6f + colsum[b * MCB + j * 32 + lane]);

    for (int r = 0; r < 32; ++r) {
        const int n = rowBase + r;
        const size_t base = ((size_t)b * HW + n) * MCB;
        const float* p = att + base;
        float v[6];
        float mx = -1e30f;
#pragma unroll
        for (int j = 0; j < 6; ++j) { v[j] = p[j * 32 + lane]; mx = fmaxf(mx, v[j]); }
#pragma unroll
        for (int o = 16; o > 0; o >>= 1) mx = fmaxf(mx, __shfl_xor_sync(0xffffffffu, mx, o));
        float s = 0.f;
#pragma unroll
        for (int j = 0; j < 6; ++j) { v[j] = expf(v[j] - mx); s += v[j]; }
#pragma unroll
        for (int o = 16; o > 0; o >>= 1) s += __shfl_xor_sync(0xffffffffu, s, o);
        const float inv = 1.f / s;
#pragma unroll
        for (int j = 0; j < 6; ++j) {
            float ov = v[j] * inv * rinv[j];
            bf16 hh, ll;
            split1(ov, hh, ll);
            oh[base + j * 32 + lane] = hh;
            ol[base + j * 32 + lane] = ll;
        }
    }
}

// ---------------- BN ----------------
__global__ void zero_stats_kernel(float* sum, float* sum2)
{
    int i = blockIdx.x * 512 + threadIdx.x;
    if (i < CIN) { sum[i] = 0.f; sum2[i] = 0.f; }
}
__global__ void bn_finalize_kernel(const float* __restrict__ sum, const float* __restrict__ sum2,
                                   const float* __restrict__ gamma, const float* __restrict__ beta,
                                   float* __restrict__ scale, float* __restrict__ shift)
{
    int c = threadIdx.x;
    const float N = (float)((size_t)BB * HW);
    float mean = sum[c] / N;
    float var = sum2[c] / N - mean * mean;
    float sc = gamma[c] * rsqrtf(var + EPS_BN);
    scale[c] = sc;
    shift[c] = beta[c] - mean * sc;
}
__global__ void bn_apply_res_split(const float* __restrict__ t,
                                   const bf16* __restrict__ xh, const bf16* __restrict__ xl,
                                   const float* __restrict__ scale, const float* __restrict__ shift,
                                   bf16* __restrict__ oh, bf16* __restrict__ ol)
{
    size_t i = (size_t)blockIdx.x * blockDim.x + threadIdx.x;   // float4 index
    const int c4 = (int)(i & 127);
    const float4 sc = ((const float4*)scale)[c4];
    const float4 sh = ((const float4*)shift)[c4];
    float4 v = ((const float4*)t)[i];
    uint2 xhu = *(const uint2*)(xh + i * 4);
    uint2 xlu = *(const uint2*)(xl + i * 4);
    __nv_bfloat162 xh0 = *(__nv_bfloat162*)&xhu.x;
    __nv_bfloat162 xh1 = *(__nv_bfloat162*)&xhu.y;
    __nv_bfloat162 xl0 = *(__nv_bfloat162*)&xlu.x;
    __nv_bfloat162 xl1 = *(__nv_bfloat162*)&xlu.y;
    v.x = fmaxf(fmaf(sc.x, v.x, sh.x), 0.f) + __bfloat162float(xh0.x) + __bfloat162float(xl0.x);
    v.y = fmaxf(fmaf(sc.y, v.y, sh.y), 0.f) + __bfloat162float(xh0.y) + __bfloat162float(xl0.y);
    v.z = fmaxf(fmaf(sc.z, v.z, sh.z), 0.f) + __bfloat162float(xh1.x) + __bfloat162float(xl1.x);
    v.w = fmaxf(fmaf(sc.w, v.w, sh.w), 0.f) + __bfloat162float(xh1.y) + __bfloat162float(xl1.y);
    bf16 hx, lx, hy, ly, hz, lz, hw, lw;
    split1(v.x, hx, lx); split1(v.y, hy, ly); split1(v.z, hz, lz); split1(v.w, hw, lw);
    uint2 ho = { pack_bf2(__bfloat162float(hx), __bfloat162float(hy)),
                 pack_bf2(__bfloat162float(hz), __bfloat162float(hw)) };
    uint2 lo = { pack_bf2(__bfloat162float(lx), __bfloat162float(ly)),
                 pack_bf2(__bfloat162float(lz), __bfloat162float(lw)) };
    *(uint2*)(oh + i * 4) = ho;
    *(uint2*)(ol + i * 4) = lo;
}

__global__ void bn_apply_transpose_kernel(const float* __restrict__ in,
                                          const float* __restrict__ scale, const float* __restrict__ shift,
                                          float* __restrict__ out)
{
    __shared__ float t[32][33];
    const int b = blockIdx.z;
    const int n0 = blockIdx.x * 32, c0 = blockIdx.y * 32;
    const float* ip = in + (size_t)b * HW * CIN;
    float* op = out + (size_t)b * CIN * HW;
    const int c = c0 + threadIdx.x;
    const float sc = scale[c], sh = shift[c];
#pragma unroll
    for (int i = 0; i < 32; i += 8) {
        float v = ip[(size_t)(n0 + threadIdx.y + i) * CIN + c];
        t[threadIdx.y + i][threadIdx.x] = fmaxf(fmaf(sc, v, sh), 0.f);
    }
    __syncthreads();
#pragma unroll
    for (int i = 0; i < 32; i += 8)
        op[(size_t)(c0 + threadIdx.y + i) * HW + n0 + threadIdx.x] = t[threadIdx.x][threadIdx.y + i];
}

// ---------------- launch ----------------
extern "C" void kernel_launch(void* const* d_in, const int* in_sizes, int n_in,
                              void* d_out, int out_size)
{
    const float* x       = (const float*)d_in[0];
    const float* centers = (const float*)d_in[1];
    const float* conv1_w = (const float*)d_in[2];
    const float* conv1_b = (const float*)d_in[3];
    const float* conv2_w = (const float*)d_in[4];
    const float* bn2_g   = (const float*)d_in[5];
    const float* bn2_b   = (const float*)d_in[6];
    const float* conv3_w = (const float*)d_in[7];
    const float* conv3_b = (const float*)d_in[8];
    const float* bn3_g   = (const float*)d_in[9];
    const float* bn3_b   = (const float*)d_in[10];
    float* out = (float*)d_out;

    bf16 *xTh, *xTl, *b1h, *b1l, *b2h, *b2l, *atth, *attl, *cth, *ctl, *ch, *cl;
    bf16 *w1h, *w1l, *w2h, *w2l, *w3h, *w3l;
    float *buf1, *att, *colsum, *sum, *sum2, *scale, *shift;
    cudaGetSymbolAddress((void**)&xTh, g_xT_h);  cudaGetSymbolAddress((void**)&xTl, g_xT_l);
    cudaGetSymbolAddress((void**)&b1h, g_b1_h);  cudaGetSymbolAddress((void**)&b1l, g_b1_l);
    cudaGetSymbolAddress((void**)&b2h, g_b2_h);  cudaGetSymbolAddress((void**)&b2l, g_b2_l);
    cudaGetSymbolAddress((void**)&atth, g_att_h); cudaGetSymbolAddress((void**)&attl, g_att_l);
    cudaGetSymbolAddress((void**)&cth, g_ct_h);  cudaGetSymbolAddress((void**)&ctl, g_ct_l);
    cudaGetSymbolAddress((void**)&ch, g_c_h);    cudaGetSymbolAddress((void**)&cl, g_c_l);
    cudaGetSymbolAddress((void**)&w1h, g_w1_h);  cudaGetSymbolAddress((void**)&w1l, g_w1_l);
    cudaGetSymbolAddress((void**)&w2h, g_w2_h);  cudaGetSymbolAddress((void**)&w2l, g_w2_l);
    cudaGetSymbolAddress((void**)&w3h, g_w3_h);  cudaGetSymbolAddress((void**)&w3l, g_w3_l);
    cudaGetSymbolAddress((void**)&buf1, g_buf1);
    cudaGetSymbolAddress((void**)&att, g_att);
    cudaGetSymbolAddress((void**)&colsum, g_colsum);
    cudaGetSymbolAddress((void**)&sum, g_sum);
    cudaGetSymbolAddress((void**)&sum2, g_sum2);
    cudaGetSymbolAddress((void**)&scale, g_scale);
    cudaGetSymbolAddress((void**)&shift, g_shift);

    const size_t S  = (size_t)HW * CIN;
    const size_t SA = (size_t)HW * MCB;

    const int SM128 = 3 * 32768;
    const int SM96  = 3 * 28672;
    cudaFuncSetAttribute(gemm_sp<128, true,  true,  false>, cudaFuncAttributeMaxDynamicSharedMemorySize, SM128);
    cudaFuncSetAttribute(gemm_sp<96,  false, false, false>, cudaFuncAttributeMaxDynamicSharedMemorySize, SM96);
    cudaFuncSetAttribute(gemm_sp<128, false, true,  false>, cudaFuncAttributeMaxDynamicSharedMemorySize, SM128);
    cudaFuncSetAttribute(gemm_sp<128, false, false, true >, cudaFuncAttributeMaxDynamicSharedMemorySize, SM128);
    cudaFuncSetAttribute(gemm_sp<128, true,  false, true >, cudaFuncAttributeMaxDynamicSharedMemorySize, SM128);

    // 0. prep
    transpose_in_split<<<dim3(HW / 32, CIN / 32, BB), dim3(32, 8)>>>(x, xTh, xTl);
    transpose_centers_split<<<(COUT * MCB + 255) / 256, 256>>>(centers, cth, ctl);
    split_kernel<<<(COUT * MCB + 255) / 256, 256>>>(centers, ch, cl, COUT * MCB);
    split_kernel<<<(COUT * CIN + 255) / 256, 256>>>(conv1_w, w1h, w1l, COUT * CIN);
    split_kernel<<<(CIN * COUT + 255) / 256, 256>>>(conv2_w, w2h, w2l, CIN * COUT);
    split_kernel<<<(CIN * CIN + 255) / 256, 256>>>(conv3_w, w3h, w3l, CIN * CIN);

    // 1. conv1 -> split buf1 planes
    gemm_sp<128, true, true, false><<<dim3(4, 32, BB), 256, SM128>>>(
        xTh, xTl, w1h, w1l, conv1_b, nullptr, b1h, b1l, nullptr, nullptr, CIN, COUT, S, S);

    // 2. att raw -> fp32 att
    gemm_sp<96, false, false, false><<<dim3(2, 32, BB), 256, SM96>>>(
        b1h, b1l, cth, ctl, nullptr, att, nullptr, nullptr, nullptr, nullptr, COUT, MCB, S, SA);

    // 3. softmax: colsum pass, then recompute+scale+split pass
    zero_colsum_kernel<<<3, 1024>>>(colsum);
    softmax_colsum_pass1<<<dim3(HW / 256, BB), 256>>>(att, colsum);
    softmax_scale_split<<<dim3(HW / 256, BB), 256>>>(att, colsum, atth, attl);

    // 4. recon -> split buf2 planes
    gemm_sp<128, false, true, false><<<dim3(4, 32, BB), 256, SM128>>>(
        atth, attl, ch, cl, nullptr, nullptr, b2h, b2l, nullptr, nullptr, MCB, COUT, SA, S);

    // 5. conv2 -> fp32 buf1 (+fused BN stats)
    zero_stats_kernel<<<1, 512>>>(sum, sum2);
    gemm_sp<128, false, false, true><<<dim3(4, 32, BB), 256, SM128>>>(
        b2h, b2l, w2h, w2l, nullptr, buf1, nullptr, nullptr, sum, sum2, COUT, CIN, S, S);

    // 6. BN2 finalize + apply (+ReLU +residual) -> split buf2
    bn_finalize_kernel<<<1, 512>>>(sum, sum2, bn2_g, bn2_b, scale, shift);
    bn_apply_res_split<<<(unsigned)(((size_t)BB * S / 4) / 256), 256>>>(buf1, xTh, xTl, scale, shift, b2h, b2l);

    // 7. conv3 -> fp32 buf1 (+fused BN stats)
    zero_stats_kernel<<<1, 512>>>(sum, sum2);
    gemm_sp<128, true, false, true><<<dim3(4, 32, BB), 256, SM128>>>(
        b2h, b2l, w3h, w3l, conv3_b, buf1, nullptr, nullptr, sum, sum2, CIN, CIN, S, S);

    // 8. BN3 finalize + apply + transpose -> out
    bn_finalize_kernel<<<1, 512>>>(sum, sum2, bn3_g, bn3_b, scale, shift);
    bn_apply_transpose_kernel<<<dim3(HW / 32, CIN / 32, BB), dim3(32, 8)>>>(buf1, scale, shift, out);
}